// round 8
// baseline (speedup 1.0000x reference)
#include <cuda_runtime.h>
#include <cuda_bf16.h>
#include <cstdint>
#include <math.h>

#define NBATCH  512
#define T       1042
#define TP      1056
#define TPQ     (TP/4)
#define KE      6400
#define KT      528
#define M_EMB   8192
#define M_PAIR  65536
#define M_REL   4096

// ---------------- scratch (device globals; no allocation) ----------------
__device__ __align__(16) float g_P[(size_t)M_EMB * TP];
__device__ __align__(16) float g_Q[(size_t)M_EMB * TP];
__device__ __align__(16) float g_H2[(size_t)M_PAIR * TP];     // f32 H2
__device__ __align__(16) float g_R[(size_t)M_EMB * TP];
__device__ __align__(16) float g_rel[(size_t)M_REL * TP];
__device__ __align__(16) float g_Hf[(size_t)M_REL * TP];
__device__ float g_fo[M_REL];
// bf16 split buffers (emb / P / Q / f path)
__device__ __align__(16) uint32_t g_taggedSp[(size_t)64 * 33 * 2048];
__device__ __align__(16) uint32_t g_WembSp[(size_t)4 * 400 * 2048];
__device__ __align__(16) uint32_t g_W1tSp[(size_t)9 * 33 * 2048];
__device__ __align__(16) uint32_t g_W1bSp[(size_t)9 * 33 * 2048];
__device__ __align__(16) uint32_t g_Wf1Sp[(size_t)9 * 66 * 2048];
// int8 2-limb buffers (L2 / L3 path). A tiles: [mt][kb][limb][512] u32;
// B tiles: [nt][kb][limb][1024] u32.
__device__ __align__(16) uint32_t g_H1I[(size_t)1024 * 33 * 1024];
__device__ __align__(16) uint32_t g_H2I[(size_t)1024 * 33 * 1024];
__device__ __align__(16) uint32_t g_W2I[(size_t)9 * 33 * 2048];
__device__ __align__(16) uint32_t g_W3I[(size_t)9 * 33 * 2048];
__device__ __align__(16) float g_saH1[M_PAIR];
__device__ __align__(16) float g_saH2[M_PAIR];
__device__ __align__(16) float g_sbW2[TP];
__device__ __align__(16) float g_sbW3[TP];
__device__ __align__(16) float g_Wf2p[TP];
__device__ __align__(16) float g_b1[TP];
__device__ __align__(16) float g_b2[TP];
__device__ __align__(16) float g_b3[TP];
__device__ __align__(16) float g_bf1[TP];

// ---------------- helpers -------------------------------------------------
__device__ __forceinline__ void split2(float a, float b, uint32_t& h, uint32_t& l) {
    __nv_bfloat16 ha = __float2bfloat16(a);
    __nv_bfloat16 hb = __float2bfloat16(b);
    float fa = __bfloat162float(ha), fb = __bfloat162float(hb);
    __nv_bfloat16 la = __float2bfloat16(a - fa);
    __nv_bfloat16 lb = __float2bfloat16(b - fb);
    h = (uint32_t)__bfloat16_as_ushort(ha) | ((uint32_t)__bfloat16_as_ushort(hb) << 16);
    l = (uint32_t)__bfloat16_as_ushort(la) | ((uint32_t)__bfloat16_as_ushort(lb) << 16);
}

__device__ __forceinline__ void mma16(float acc[4], const uint32_t a[4], const uint32_t b[2]) {
    asm volatile(
        "mma.sync.aligned.m16n8k16.row.col.f32.bf16.bf16.f32 "
        "{%0,%1,%2,%3},{%4,%5,%6,%7},{%8,%9},{%0,%1,%2,%3};"
        : "+f"(acc[0]), "+f"(acc[1]), "+f"(acc[2]), "+f"(acc[3])
        : "r"(a[0]), "r"(a[1]), "r"(a[2]), "r"(a[3]), "r"(b[0]), "r"(b[1]));
}

__device__ __forceinline__ void imma32(int acc[4], const uint32_t a[4], const uint32_t b[2]) {
    asm volatile(
        "mma.sync.aligned.m16n8k32.row.col.s32.s8.s8.s32 "
        "{%0,%1,%2,%3},{%4,%5,%6,%7},{%8,%9},{%0,%1,%2,%3};"
        : "+r"(acc[0]), "+r"(acc[1]), "+r"(acc[2]), "+r"(acc[3])
        : "r"(a[0]), "r"(a[1]), "r"(a[2]), "r"(a[3]), "r"(b[0]), "r"(b[1]));
}

// quantize v (|v| <= sa/1.0078125) to 16-bit fixed point, split limbs.
__device__ __forceinline__ void q16(float v, float inv, int& A1, int& A0) {
    int q = __float2int_rn(v * inv);
    A1 = (q + 128) >> 8;
    A0 = q - (A1 << 8);
}
__device__ __forceinline__ uint32_t pack4(int b0, int b1, int b2, int b3) {
    return (uint32_t)(b0 & 0xff) | ((uint32_t)(b1 & 0xff) << 8) |
           ((uint32_t)(b2 & 0xff) << 16) | ((uint32_t)(b3 & 0xff) << 24);
}

// ================= 3x-BF16 mma.sync GEMM (emb / P / Q / f) ================
template<int EPI, int ASRC, int AOUT, int NF>
__device__ __forceinline__ void gemm_body(
    const float* __restrict__ A, int lda,
    const uint32_t* __restrict__ Asp,
    const uint32_t* __restrict__ Bsp,
    int Ncols, float* __restrict__ C, int ldc,
    uint32_t* __restrict__ Csp, int KBC,
    int K, const float* __restrict__ bias,
    uint32_t* smu)
{
    constexpr int A_HI = 0;
    constexpr int A_LO = 1032;
    constexpr int B_HI = 2064;
    constexpr int B_LO = 3096;
    constexpr int STG  = 4128;

    const int t  = threadIdx.x;
    const int m0 = blockIdx.y * 128, n0 = blockIdx.x * 128;
    const int KB = K >> 4;

    const int prow = t >> 1, pks = t & 1;
    const int p8 = prow & 7, rb8 = (prow >> 3) & 1, fb = prow >> 4;
    const float* ApA = nullptr;
    if (ASRC == 0) ApA = A + (size_t)(m0 + prow) * lda + pks * 8;

    float va[8];
    uint4 hA, lA, hB, lB;

    const int L = t & 31, wid = t >> 5, wm = wid >> 2, wn = wid & 3;
    float acc[4][NF][4];
    #pragma unroll
    for (int i = 0; i < 4; i++)
        #pragma unroll
        for (int j = 0; j < NF; j++)
            #pragma unroll
            for (int v = 0; v < 4; v++) acc[i][j][v] = 0.f;

    auto ldtile = [&](int kb) {
        const uint32_t* gB = Bsp + ((size_t)(blockIdx.x * KB + kb)) * 2048;
        if (NF == 4) {
            hB = ((const uint4*)gB)[t];
            lB = ((const uint4*)gB)[256 + t];
        } else {
            hB.x = gB[t];
            lB.x = gB[1024 + t];
        }
        if (ASRC == 2) {
            const uint4* gA = (const uint4*)(Asp + ((size_t)(blockIdx.y * KB + kb)) * 2048);
            hA = gA[t]; lA = gA[256 + t];
        } else {
            int k0 = kb * 16;
            float4 x0 = *(const float4*)(ApA + k0);
            float4 x1 = *(const float4*)(ApA + k0 + 4);
            va[0] = x0.x; va[1] = x0.y; va[2] = x0.z; va[3] = x0.w;
            va[4] = x1.x; va[5] = x1.y; va[6] = x1.z; va[7] = x1.w;
        }
    };

    auto sttile = [&](uint32_t* stg) {
        if (NF == 4) {
            *(uint4*)(stg + B_HI + t * 4) = hB;
            *(uint4*)(stg + B_LO + t * 4) = lB;
        } else {
            stg[B_HI + t] = hB.x;
            stg[B_LO + t] = lB.x;
        }
        if (ASRC == 2) {
            *(uint4*)(stg + A_HI + t * 4) = hA;
            *(uint4*)(stg + A_LO + t * 4) = lA;
        } else {
            #pragma unroll
            for (int j = 0; j < 4; j++) {
                uint32_t h, l;
                split2(va[2 * j], va[2 * j + 1], h, l);
                int ai = fb * 128 + (p8 * 4 + j) * 4 + rb8 + 2 * pks;
                stg[A_HI + ai] = h;
                stg[A_LO + ai] = l;
            }
        }
    };

    auto consume = [&](const uint32_t* stg) {
        uint32_t ah[4][4], al[4][4], bh[NF][2], bl[NF][2];
        #pragma unroll
        for (int mf = 0; mf < 4; mf++) {
            const uint32_t* ab = stg + (wm * 4 + mf) * 128 + L * 4;
            *(uint4*)ah[mf] = *(const uint4*)(ab + A_HI);
            *(uint4*)al[mf] = *(const uint4*)(ab + A_LO);
        }
        #pragma unroll
        for (int nf = 0; nf < NF; nf++) {
            const uint32_t* bb = stg + (wn * NF + nf) * 64 + L * 2;
            *(uint2*)bh[nf] = *(const uint2*)(bb + B_HI);
            *(uint2*)bl[nf] = *(const uint2*)(bb + B_LO);
        }
        #pragma unroll
        for (int mf = 0; mf < 4; mf++)
            #pragma unroll
            for (int nf = 0; nf < NF; nf++) {
                mma16(acc[mf][nf], ah[mf], bh[nf]);
                mma16(acc[mf][nf], ah[mf], bl[nf]);
                mma16(acc[mf][nf], al[mf], bh[nf]);
            }
    };

    ldtile(0);
    sttile(smu);
    __syncthreads();
    for (int kb = 0; kb < KB; kb++) {
        if (kb + 1 < KB) ldtile(kb + 1);
        consume(smu + (kb & 1) * STG);
        if (kb + 1 < KB) sttile(smu + ((kb + 1) & 1) * STG);
        __syncthreads();
    }

    const int baseRow = m0 + wm * 64;

    if (AOUT == 1) {
        const int mt = blockIdx.y;
        #pragma unroll
        for (int mf = 0; mf < 4; mf++) {
            #pragma unroll
            for (int f = 0; f < 2; f++) {
                int kbC = (n0 >> 4) + wn * 2 + f;
                if (kbC < KBC) {
                    uint32_t hi[4], lo[4];
                    #pragma unroll
                    for (int s = 0; s < 2; s++) {
                        int nf = 2 * f + s;
                        int col = n0 + wn * 32 + nf * 8 + (L & 3) * 2;
                        float c0 = acc[mf][nf][0], c1 = acc[mf][nf][1];
                        float c2 = acc[mf][nf][2], c3 = acc[mf][nf][3];
                        if (EPI >= 1) {
                            float2 b2 = *(const float2*)(bias + col);
                            c0 += b2.x; c1 += b2.y; c2 += b2.x; c3 += b2.y;
                        }
                        if (EPI >= 2) {
                            c0 = fmaxf(c0, 0.f); c1 = fmaxf(c1, 0.f);
                            c2 = fmaxf(c2, 0.f); c3 = fmaxf(c3, 0.f);
                        }
                        split2(c0, c1, hi[2 * s], lo[2 * s]);
                        split2(c2, c3, hi[2 * s + 1], lo[2 * s + 1]);
                    }
                    size_t base = ((size_t)mt * KBC + kbC) * 2048 + (wm * 4 + mf) * 128 + L * 4;
                    *(uint4*)(Csp + base)        = make_uint4(hi[0], hi[1], hi[2], hi[3]);
                    *(uint4*)(Csp + base + 1024) = make_uint4(lo[0], lo[1], lo[2], lo[3]);
                }
            }
        }
        return;
    }

    #pragma unroll
    for (int mf = 0; mf < 4; mf++) {
        #pragma unroll
        for (int nf = 0; nf < NF; nf++) {
            int col = n0 + wn * 8 * NF + nf * 8 + (L & 3) * 2;
            bool cv = col < Ncols;
            float c0 = acc[mf][nf][0], c1 = acc[mf][nf][1];
            float c2 = acc[mf][nf][2], c3 = acc[mf][nf][3];
            if (EPI >= 1) {
                float2 b2 = cv ? *(const float2*)(bias + col) : make_float2(0.f, 0.f);
                c0 += b2.x; c1 += b2.y; c2 += b2.x; c3 += b2.y;
            }
            if (EPI >= 2) {
                c0 = fmaxf(c0, 0.f); c1 = fmaxf(c1, 0.f);
                c2 = fmaxf(c2, 0.f); c3 = fmaxf(c3, 0.f);
            }
            if (cv) {
                int row = baseRow + mf * 16 + (L >> 2);
                *(float2*)(C + (size_t)row * ldc + col)       = make_float2(c0, c1);
                *(float2*)(C + (size_t)(row + 8) * ldc + col) = make_float2(c2, c3);
            }
        }
    }
}

template<int EPI, int ASRC, int AOUT, int NARROW>
__global__ void __launch_bounds__(256, 1) mmagemm_k(
    const float* __restrict__ A, int lda,
    const uint32_t* __restrict__ Asp,
    const uint32_t* __restrict__ Bsp,
    int Ncols, float* __restrict__ C, int ldc,
    uint32_t* __restrict__ Csp, int KBC,
    int K, const float* __restrict__ bias)
{
    extern __shared__ uint32_t smu[];
    if (NARROW && blockIdx.x == gridDim.x - 1)
        gemm_body<EPI, ASRC, AOUT, 1>(A, lda, Asp, Bsp, Ncols, C, ldc, Csp, KBC, K, bias, smu);
    else
        gemm_body<EPI, ASRC, AOUT, 4>(A, lda, Asp, Bsp, Ncols, C, ldc, Csp, KBC, K, bias, smu);
}

// ================= int8 2-limb IMMA GEMM (L2 / L3) ========================
// C[M x 1056] = dequant(A) @ dequant(B)^T.  BM=64, BN=128 (narrow 32).
// A: [mt][kb][limb][512] u32 s8x4; B: [nt][kb][limb][1024]; K = 1056, KB = 33.
// EPI: 2 = bias+relu -> f32 C; 3 = bias+relu+sum groups of 8 rows -> f32 C.
template<int EPI, int NF>
__device__ __forceinline__ void imma_body(
    const uint32_t* __restrict__ Asp, const float* __restrict__ saA,
    const uint32_t* __restrict__ Bsp, const float* __restrict__ sbB,
    float* __restrict__ C, int ldc, const float* __restrict__ bias,
    uint32_t* smu)
{
    constexpr int STG = 3072;
    const int t = threadIdx.x;
    const int m0 = blockIdx.y * 64, n0 = blockIdx.x * 128;
    const int KB = 33;
    const int L = t & 31, wid = t >> 5, wm = wid >> 2, wn = wid & 3;

    int accH[2][NF][4], accM[2][NF][4], accL[2][NF][4];
    #pragma unroll
    for (int i = 0; i < 2; i++)
        #pragma unroll
        for (int j = 0; j < NF; j++)
            #pragma unroll
            for (int v = 0; v < 4; v++) { accH[i][j][v] = 0; accM[i][j][v] = 0; accL[i][j][v] = 0; }

    uint4 aR, bR0, bR1;
    auto ldtile = [&](int kb) {
        aR  = ((const uint4*)(Asp + ((size_t)(blockIdx.y * KB + kb)) * 1024))[t];
        const uint4* gB = (const uint4*)(Bsp + ((size_t)(blockIdx.x * KB + kb)) * 2048);
        bR0 = gB[t]; bR1 = gB[256 + t];
    };
    auto sttile = [&](uint32_t* stg) {
        *(uint4*)(stg + t * 4) = aR;
        *(uint4*)(stg + 1024 + t * 4) = bR0;
        *(uint4*)(stg + 2048 + t * 4) = bR1;
    };
    auto consume = [&](const uint32_t* stg) {
        uint32_t a1[2][4], a0[2][4], b1[NF][2], b0[NF][2];
        #pragma unroll
        for (int mf = 0; mf < 2; mf++) {
            int fb = wm * 2 + mf;
            *(uint4*)a1[mf] = *(const uint4*)(stg + fb * 128 + L * 4);
            *(uint4*)a0[mf] = *(const uint4*)(stg + 512 + fb * 128 + L * 4);
        }
        #pragma unroll
        for (int nf = 0; nf < NF; nf++) {
            int off = (wn * NF + nf) * 64 + L * 2;
            *(uint2*)b1[nf] = *(const uint2*)(stg + 1024 + off);
            *(uint2*)b0[nf] = *(const uint2*)(stg + 2048 + off);
        }
        #pragma unroll
        for (int mf = 0; mf < 2; mf++)
            #pragma unroll
            for (int nf = 0; nf < NF; nf++) {
                imma32(accH[mf][nf], a1[mf], b1[nf]);
                imma32(accM[mf][nf], a1[mf], b0[nf]);
                imma32(accM[mf][nf], a0[mf], b1[nf]);
                imma32(accL[mf][nf], a0[mf], b0[nf]);
            }
    };

    ldtile(0);
    sttile(smu);
    __syncthreads();
    for (int kb = 0; kb < KB; kb++) {
        if (kb + 1 < KB) ldtile(kb + 1);
        consume(smu + (kb & 1) * STG);
        if (kb + 1 < KB) sttile(smu + ((kb + 1) & 1) * STG);
        __syncthreads();
    }

    const float C14 = 6.103515625e-5f;          // 2^-14
    const float C22 = 2.384185791015625e-7f;    // 2^-22
    const float C30 = 9.313225746154785e-10f;   // 2^-30

    #pragma unroll
    for (int mf = 0; mf < 2; mf++) {
        int rbase = m0 + wm * 32 + mf * 16;
        int r0 = rbase + (L >> 2);
        float sa0 = saA[r0], sa8 = saA[r0 + 8];
        #pragma unroll
        for (int nf = 0; nf < NF; nf++) {
            int col = n0 + wn * NF * 8 + nf * 8 + (L & 3) * 2;
            float sb0 = sbB[col], sb1 = sbB[col + 1];
            float g0 = (float)accH[mf][nf][0] * C14 + (float)accM[mf][nf][0] * C22 + (float)accL[mf][nf][0] * C30;
            float g1 = (float)accH[mf][nf][1] * C14 + (float)accM[mf][nf][1] * C22 + (float)accL[mf][nf][1] * C30;
            float g2 = (float)accH[mf][nf][2] * C14 + (float)accM[mf][nf][2] * C22 + (float)accL[mf][nf][2] * C30;
            float g3 = (float)accH[mf][nf][3] * C14 + (float)accM[mf][nf][3] * C22 + (float)accL[mf][nf][3] * C30;
            float2 b2 = *(const float2*)(bias + col);
            float c0 = fmaxf(sa0 * sb0 * g0 + b2.x, 0.f);
            float c1 = fmaxf(sa0 * sb1 * g1 + b2.y, 0.f);
            float c2 = fmaxf(sa8 * sb0 * g2 + b2.x, 0.f);
            float c3 = fmaxf(sa8 * sb1 * g3 + b2.y, 0.f);
            if (EPI == 3) {
                c0 += __shfl_down_sync(0xffffffffu, c0, 16);
                c0 += __shfl_down_sync(0xffffffffu, c0, 8);
                c0 += __shfl_down_sync(0xffffffffu, c0, 4);
                c1 += __shfl_down_sync(0xffffffffu, c1, 16);
                c1 += __shfl_down_sync(0xffffffffu, c1, 8);
                c1 += __shfl_down_sync(0xffffffffu, c1, 4);
                c2 += __shfl_down_sync(0xffffffffu, c2, 16);
                c2 += __shfl_down_sync(0xffffffffu, c2, 8);
                c2 += __shfl_down_sync(0xffffffffu, c2, 4);
                c3 += __shfl_down_sync(0xffffffffu, c3, 16);
                c3 += __shfl_down_sync(0xffffffffu, c3, 8);
                c3 += __shfl_down_sync(0xffffffffu, c3, 4);
                if (L < 4) {
                    int g = rbase >> 3;
                    *(float2*)(C + (size_t)g * ldc + col)       = make_float2(c0, c1);
                    *(float2*)(C + (size_t)(g + 1) * ldc + col) = make_float2(c2, c3);
                }
            } else {
                *(float2*)(C + (size_t)r0 * ldc + col)       = make_float2(c0, c1);
                *(float2*)(C + (size_t)(r0 + 8) * ldc + col) = make_float2(c2, c3);
            }
        }
    }
}

template<int EPI>
__global__ void __launch_bounds__(256, 1) imma_k(
    const uint32_t* __restrict__ Asp, const float* __restrict__ saA,
    const uint32_t* __restrict__ Bsp, const float* __restrict__ sbB,
    float* __restrict__ C, int ldc, const float* __restrict__ bias)
{
    __shared__ uint32_t smu[2 * 3072];
    if (blockIdx.x == gridDim.x - 1)
        imma_body<EPI, 1>(Asp, saA, Bsp, sbB, C, ldc, bias, smu);
    else
        imma_body<EPI, 4>(Asp, saA, Bsp, sbB, C, ldc, bias, smu);
}

// ============ bf16 weight transpose + split + fragment-permute ============
__global__ void wsplit_k(uint32_t* __restrict__ dst, const float* __restrict__ src,
                         int NT, int KB, int sK, int sN, int sStride, int rowOff)
{
    int idx = blockIdx.x * blockDim.x + threadIdx.x;
    if (idx >= NT * KB * 1024) return;
    int bi  = idx & 1023;
    int pks = bi & 1;
    int lj  = (bi >> 1) & 31;
    int nb  = bi >> 6;
    int p8  = lj >> 2, j = lj & 3;
    int nt  = idx / (KB * 1024);
    int kb  = (idx >> 10) % KB;
    int n = nt * 128 + nb * 8 + p8;
    int k = kb * 16 + pks * 8 + 2 * j;
    float w0 = (k < sK && n < sN)     ? src[(size_t)(k + rowOff) * sStride + n]     : 0.f;
    float w1 = (k + 1 < sK && n < sN) ? src[(size_t)(k + 1 + rowOff) * sStride + n] : 0.f;
    uint32_t h, l;
    split2(w0, w1, h, l);
    size_t base = ((size_t)(idx >> 10)) * 2048 + bi;
    dst[base] = h;
    dst[base + 1024] = l;
}

// ============ int8 weight prep: colmax + quantize/permute =================
__global__ void wcolmax_k(float* __restrict__ sb, const float* __restrict__ W)
{
    __shared__ float sm[8][32];
    int c = blockIdx.x * 32 + (threadIdx.x & 31);
    int r0 = threadIdx.x >> 5;
    float m = 0.f;
    if (c < T)
        for (int r = r0; r < T; r += 8) m = fmaxf(m, fabsf(W[(size_t)r * T + c]));
    sm[r0][threadIdx.x & 31] = m;
    __syncthreads();
    if (threadIdx.x < 32) {
        float mm = sm[0][threadIdx.x];
        #pragma unroll
        for (int i = 1; i < 8; i++) mm = fmaxf(mm, sm[i][threadIdx.x]);
        sb[blockIdx.x * 32 + threadIdx.x] = fmaxf(mm, 1e-30f) * 1.0078125f;
    }
}

__global__ void wquant8_k(uint32_t* __restrict__ WI, const float* __restrict__ W,
                          const float* __restrict__ sb)
{
    int idx = blockIdx.x * blockDim.x + threadIdx.x;   // 9*33*1024
    if (idx >= 9 * 33 * 1024) return;
    int bi = idx & 1023;
    int nb = bi >> 6, lane = (bi >> 1) & 31, reg = bi & 1;
    int kb = (idx >> 10) % 33;
    int nt = idx / (33 * 1024);
    int col = nt * 128 + nb * 8 + (lane >> 2);
    int kbase = kb * 32 + reg * 16 + (lane & 3) * 4;
    float inv = 32768.0f / sb[col];
    int h[4], l[4];
    #pragma unroll
    for (int byte = 0; byte < 4; byte++) {
        int k = kbase + byte;
        float w = (k < T && col < T) ? W[(size_t)k * T + col] : 0.f;
        q16(w, inv, h[byte], l[byte]);
    }
    size_t base = ((size_t)(nt * 33 + kb)) * 2048;
    int i2 = nb * 64 + lane * 2 + reg;
    WI[base + i2] = pack4(h[0], h[1], h[2], h[3]);
    WI[base + 1024 + i2] = pack4(l[0], l[1], l[2], l[3]);
}

// ---- tag one-hot into taggedSp kb 32 (cols 512..527) ---------------------
__global__ void tagsplit_k(uint32_t* __restrict__ tsp)
{
    int idx = blockIdx.x * blockDim.x + threadIdx.x;   // 64 * 1024
    if (idx >= 64 * 1024) return;
    int ai = idx & 1023;
    int mt = idx >> 10;
    int w = ai & 127, fbv = ai >> 7;
    int lane = w >> 2, rem = w & 3;
    int rb8 = rem & 1, pks = rem >> 1;
    int p8 = lane >> 2, j = lane & 3;
    int r = mt * 128 + fbv * 16 + rb8 * 8 + p8;
    int col = 512 + pks * 8 + 2 * j;
    int tpos = ((r & 15) < 8) ? (r & 15) : 8;
    int tcol = 512 + tpos;
    uint32_t h = 0;
    if (col == tcol)     h |= 0x3F80u;
    if (col + 1 == tcol) h |= 0x3F80u << 16;
    size_t base = ((size_t)mt * 33 + 32) * 2048 + ai;
    tsp[base] = h;
    tsp[base + 1024] = 0u;
}

// ---- exact rowmax of relu(P[b,j]+Q[b,k]+b1) -> saH1 ----------------------
__global__ void rowmaxH1_k(const float* __restrict__ P, const float* __restrict__ Q,
                           const float* __restrict__ b1, float* __restrict__ saH1)
{
    int b = blockIdx.x;
    int t = threadIdx.x;
    int r = t >> 1, half = t & 1;
    const float* Pp = P + (size_t)(b * 16 + (r & 7)) * TP;
    const float* Qp = Q + (size_t)(b * 16 + (r >> 3)) * TP;
    float m = 0.f;
    int c0 = half * 528;
    for (int c = c0; c < c0 + 528; c++)
        m = fmaxf(m, Pp[c] + Qp[c] + b1[c]);
    m = fmaxf(m, __shfl_xor_sync(0xffffffffu, m, 1));
    if (half == 0) saH1[b * 128 + r] = fmaxf(m, 1e-30f) * 1.0078125f;
}

// ---- H1 expand + int8 quantize + A-permute -------------------------------
__global__ void expand8_k(const float* __restrict__ P, const float* __restrict__ Q,
                          const float* __restrict__ b1, const float* __restrict__ saH1,
                          uint32_t* __restrict__ H1I)
{
    __shared__ float sP[8][32], sQ[16][32], sB[32];
    int kb = blockIdx.x, b = blockIdx.y;
    int t = threadIdx.x;
    int k0 = kb * 32;
    if (t < 192) {
        int row = t >> 3, q8 = t & 7;
        const float* src = (row < 8) ? (P + (size_t)(b * 16 + row) * TP)
                                     : (Q + (size_t)(b * 16 + row - 8) * TP);
        float4 v = *(const float4*)(src + k0 + q8 * 4);
        if (row < 8) *(float4*)&sP[row][q8 * 4] = v;
        else         *(float4*)&sQ[row - 8][q8 * 4] = v;
    } else if (t < 200) {
        int q8 = t - 192;
        *(float4*)&sB[q8 * 4] = *(const float4*)(b1 + k0 + q8 * 4);
    }
    __syncthreads();
    int r = t >> 1, kh = t & 1;
    int jj = r & 7, kk = r >> 3;
    float inv = 32768.0f / saH1[b * 128 + r];
    int rr64 = r & 63;
    int mt = b * 2 + (r >> 6);
    int fb = rr64 >> 4, rr = rr64 & 15;
    int reg = (rr >> 3) + 2 * kh;
    size_t base = ((size_t)mt * 33 + kb) * 1024;
    #pragma unroll
    for (int q = 0; q < 4; q++) {
        int h[4], l[4];
        #pragma unroll
        for (int byte = 0; byte < 4; byte++) {
            int k = kh * 16 + q * 4 + byte;
            float e = fmaxf(sP[jj][k] + sQ[kk][k] + sB[k], 0.f);
            q16(e, inv, h[byte], l[byte]);
        }
        int idx = fb * 128 + ((rr & 7) * 4 + q) * 4 + reg;
        H1I[base + idx] = pack4(h[0], h[1], h[2], h[3]);
        H1I[base + 512 + idx] = pack4(l[0], l[1], l[2], l[3]);
    }
}

// ---- rowmax of f32 H2 -> saH2 --------------------------------------------
__global__ void rowmaxH2_k(const float* __restrict__ H2, float* __restrict__ saH2)
{
    int w = threadIdx.x >> 5, L = threadIdx.x & 31;
    int row = blockIdx.x * 8 + w;
    const float* h = H2 + (size_t)row * TP;
    float m = 0.f;
    for (int c = L; c < TP; c += 32) m = fmaxf(m, h[c]);
    #pragma unroll
    for (int o = 16; o; o >>= 1) m = fmaxf(m, __shfl_down_sync(0xffffffffu, m, o));
    if (L == 0) saH2[row] = fmaxf(m, 1e-30f) * 1.0078125f;
}

// ---- quantize f32 H2 -> int8 limbs (A-permuted) --------------------------
__global__ void quant8_k(const float* __restrict__ H2, const float* __restrict__ saH2,
                         uint32_t* __restrict__ H2I)
{
    int kb = blockIdx.x, mt = blockIdx.y;
    int t = threadIdx.x;
    int r = t >> 2, qt = t & 3;
    int row = mt * 64 + r;
    const float* src = H2 + (size_t)row * TP + kb * 32 + qt * 8;
    float4 v0 = *(const float4*)src;
    float4 v1 = *(const float4*)(src + 4);
    float e[8] = {v0.x, v0.y, v0.z, v0.w, v1.x, v1.y, v1.z, v1.w};
    float inv = 32768.0f / saH2[row];
    int kh = qt >> 1, qbase = (qt & 1) * 2;
    int fb = r >> 4, rr = r & 15;
    int reg = (rr >> 3) + 2 * kh;
    size_t base = ((size_t)mt * 33 + kb) * 1024;
    #pragma unroll
    for (int p = 0; p < 2; p++) {
        int h[4], l[4];
        #pragma unroll
        for (int byte = 0; byte < 4; byte++)
            q16(e[p * 4 + byte], inv, h[byte], l[byte]);
        int q = qbase + p;
        int idx = fb * 128 + ((rr & 7) * 4 + q) * 4 + reg;
        H2I[base + idx] = pack4(h[0], h[1], h[2], h[3]);
        H2I[base + 512 + idx] = pack4(l[0], l[1], l[2], l[3]);
    }
}

// ======================= small kernels ====================================
__global__ void pad2d_k(float* __restrict__ dst, const float* __restrict__ src,
                        int dR, int dC, int sR, int sC, int sStride, int sRowOff)
{
    int idx = blockIdx.x * blockDim.x + threadIdx.x;
    if (idx >= dR * dC) return;
    int r = idx / dC, c = idx % dC;
    float v = 0.f;
    if (r < sR && c < sC) v = src[(size_t)(r + sRowOff) * sStride + c];
    dst[idx] = v;
}

__global__ void relations_k(const float* __restrict__ R, float* __restrict__ rel)
{
    int idx = blockIdx.x * blockDim.x + threadIdx.x;
    if (idx >= NBATCH * TPQ) return;
    int c4 = idx % TPQ;
    int b  = idx / TPQ;
    const float4* r = reinterpret_cast<const float4*>(R) + (size_t)(b * 16) * TPQ + c4;
    float4 cs = make_float4(0.f, 0.f, 0.f, 0.f);
    #pragma unroll
    for (int k = 0; k < 8; k++) {
        float4 v = r[(size_t)k * TPQ];
        cs.x += v.x; cs.y += v.y; cs.z += v.z; cs.w += v.w;
    }
    #pragma unroll
    for (int a = 0; a < 8; a++) {
        float4 v = r[(size_t)(8 + a) * TPQ];
        float4 o = make_float4(cs.x + v.x, cs.y + v.y, cs.z + v.z, cs.w + v.w);
        reinterpret_cast<float4*>(rel)[(size_t)(b * 8 + a) * TPQ + c4] = o;
    }
}

__inline__ __device__ float warp_sum(float v)
{
    #pragma unroll
    for (int o = 16; o; o >>= 1) v += __shfl_down_sync(0xffffffffu, v, o);
    return v;
}

__global__ void fout_k(const float* __restrict__ Hf, const float* __restrict__ W,
                       const float* __restrict__ bf2, float* __restrict__ fo)
{
    int row = blockIdx.x;
    const float* h = Hf + (size_t)row * TP;
    float s = 0.f;
    for (int c = threadIdx.x; c < TP; c += 128) s += h[c] * W[c];
    s = warp_sum(s);
    __shared__ float sh[4];
    if ((threadIdx.x & 31) == 0) sh[threadIdx.x >> 5] = s;
    __syncthreads();
    if (threadIdx.x == 0) fo[row] = sh[0] + sh[1] + sh[2] + sh[3] + bf2[0];
}

__global__ void loss_k(const float* __restrict__ fo, const int* __restrict__ labels,
                       float* __restrict__ out)
{
    int b = threadIdx.x;
    int lab = labels[b];
    float lsum = 0.f;
    float best = -1e30f; int bi = 0;
    #pragma unroll
    for (int a = 0; a < 8; a++) {
        float f = fo[b * 8 + a];
        float l = fmaxf(f, 0.f) - f * ((a == lab) ? 1.f : 0.f) + log1pf(expf(-fabsf(f)));
        lsum += l;
        if (f > best) { best = f; bi = a; }
    }
    float cor = (bi == lab) ? 1.f : 0.f;
    lsum = warp_sum(lsum);
    cor  = warp_sum(cor);
    __shared__ float sl[16], sc[16];
    int wid = threadIdx.x >> 5, lane = threadIdx.x & 31;
    if (lane == 0) { sl[wid] = lsum; sc[wid] = cor; }
    __syncthreads();
    if (wid == 0) {
        float a = (lane < 16) ? sl[lane] : 0.f;
        float c = (lane < 16) ? sc[lane] : 0.f;
        a = warp_sum(a);
        c = warp_sum(c);
        if (lane == 0) {
            out[0] = a / (float)(NBATCH * 8);
            out[1] = c / (float)NBATCH;
        }
    }
}

// ======================= host =============================================
static inline int cdiv(int a, int b) { return (a + b - 1) / b; }

extern "C" void kernel_launch(void* const* d_in, const int* in_sizes, int n_in,
                              void* d_out, int out_size)
{
    const float* x      = (const float*)d_in[0];
    const float* W_emb  = (const float*)d_in[1];
    const float* b_emb  = (const float*)d_in[2];
    const float* Wg1    = (const float*)d_in[3];
    const float* bg1    = (const float*)d_in[4];
    const float* Wg2    = (const float*)d_in[5];
    const float* bg2    = (const float*)d_in[6];
    const float* Wg3    = (const float*)d_in[7];
    const float* bg3    = (const float*)d_in[8];
    const float* Wf1    = (const float*)d_in[9];
    const float* bf1    = (const float*)d_in[10];
    const float* Wf2    = (const float*)d_in[11];
    const float* bf2    = (const float*)d_in[12];
    const int*   labels = (const int*)d_in[13];
    float* out = (float*)d_out;

    float *P, *Q, *H2, *R, *rel, *Hf, *fo;
    float *Wf2p, *b1p, *b2p, *b3p, *bf1p;
    float *saH1, *saH2, *sbW2, *sbW3;
    uint32_t *taggedSp, *WembSp, *W1tSp, *W1bSp, *Wf1Sp;
    uint32_t *H1I, *H2I, *W2I, *W3I;
    cudaGetSymbolAddress((void**)&P, g_P);
    cudaGetSymbolAddress((void**)&Q, g_Q);
    cudaGetSymbolAddress((void**)&H2, g_H2);
    cudaGetSymbolAddress((void**)&R, g_R);
    cudaGetSymbolAddress((void**)&rel, g_rel);
    cudaGetSymbolAddress((void**)&Hf, g_Hf);
    cudaGetSymbolAddress((void**)&fo, g_fo);
    cudaGetSymbolAddress((void**)&taggedSp, g_taggedSp);
    cudaGetSymbolAddress((void**)&WembSp, g_WembSp);
    cudaGetSymbolAddress((void**)&W1tSp, g_W1tSp);
    cudaGetSymbolAddress((void**)&W1bSp, g_W1bSp);
    cudaGetSymbolAddress((void**)&Wf1Sp, g_Wf1Sp);
    cudaGetSymbolAddress((void**)&H1I, g_H1I);
    cudaGetSymbolAddress((void**)&H2I, g_H2I);
    cudaGetSymbolAddress((void**)&W2I, g_W2I);
    cudaGetSymbolAddress((void**)&W3I, g_W3I);
    cudaGetSymbolAddress((void**)&saH1, g_saH1);
    cudaGetSymbolAddress((void**)&saH2, g_saH2);
    cudaGetSymbolAddress((void**)&sbW2, g_sbW2);
    cudaGetSymbolAddress((void**)&sbW3, g_sbW3);
    cudaGetSymbolAddress((void**)&Wf2p, g_Wf2p);
    cudaGetSymbolAddress((void**)&b1p, g_b1);
    cudaGetSymbolAddress((void**)&b2p, g_b2);
    cudaGetSymbolAddress((void**)&b3p, g_b3);
    cudaGetSymbolAddress((void**)&bf1p, g_bf1);

    const int SMB = 2 * 4128 * 4;
    cudaFuncSetAttribute(mmagemm_k<1,0,1,0>, cudaFuncAttributeMaxDynamicSharedMemorySize, SMB);
    cudaFuncSetAttribute(mmagemm_k<0,2,0,1>, cudaFuncAttributeMaxDynamicSharedMemorySize, SMB);
    cudaFuncSetAttribute(mmagemm_k<2,0,0,1>, cudaFuncAttributeMaxDynamicSharedMemorySize, SMB);

    // ---- one-time weight prep ----
    wsplit_k<<<cdiv(4 * 400 * 1024, 256), 256>>>(WembSp, W_emb, 4, 400, KE, 512, 512, 0);
    wsplit_k<<<cdiv(9 * 33 * 1024, 256), 256>>>(W1tSp, Wg1, 9, 33, 521, T, T, 0);
    wsplit_k<<<cdiv(9 * 33 * 1024, 256), 256>>>(W1bSp, Wg1, 9, 33, 521, T, T, 521);
    wsplit_k<<<cdiv(9 * 66 * 1024, 256), 256>>>(Wf1Sp, Wf1, 9, 66, T, T, T, 0);
    wcolmax_k<<<33, 256>>>(sbW2, Wg2);
    wcolmax_k<<<33, 256>>>(sbW3, Wg3);
    wquant8_k<<<cdiv(9 * 33 * 1024, 256), 256>>>(W2I, Wg2, sbW2);
    wquant8_k<<<cdiv(9 * 33 * 1024, 256), 256>>>(W3I, Wg3, sbW3);
    pad2d_k<<<cdiv(TP, 256), 256>>>(Wf2p, Wf2, 1, TP, 1, T, T, 0);
    pad2d_k<<<cdiv(TP, 256), 256>>>(b1p, bg1, 1, TP, 1, T, T, 0);
    pad2d_k<<<cdiv(TP, 256), 256>>>(b2p, bg2, 1, TP, 1, T, T, 0);
    pad2d_k<<<cdiv(TP, 256), 256>>>(b3p, bg3, 1, TP, 1, T, T, 0);
    pad2d_k<<<cdiv(TP, 256), 256>>>(bf1p, bf1, 1, TP, 1, T, T, 0);
    tagsplit_k<<<cdiv(64 * 1024, 256), 256>>>(taggedSp);

    // emb = x @ W_emb + b_emb -> taggedSp (bf16-split layout)
    mmagemm_k<1,0,1,0><<<dim3(4, M_EMB / 128), 256, SMB>>>(
        x, KE, nullptr, WembSp, 512, nullptr, 0, taggedSp, 33, KE, b_emb);
    // P, Q (bf16 path)
    mmagemm_k<0,2,0,1><<<dim3(9, M_EMB / 128), 256, SMB>>>(
        nullptr, 0, taggedSp, W1tSp, TP, P, TP, nullptr, 0, KT, nullptr);
    mmagemm_k<0,2,0,1><<<dim3(9, M_EMB / 128), 256, SMB>>>(
        nullptr, 0, taggedSp, W1bSp, TP, Q, TP, nullptr, 0, KT, nullptr);
    // H1 quantization: exact rowmax, then expand+quantize+permute
    rowmaxH1_k<<<NBATCH, 256>>>(P, Q, b1p, saH1);
    expand8_k<<<dim3(33, NBATCH), 256>>>(P, Q, b1p, saH1, H1I);
    // L2: H2 = relu(H1 @ Wg2 + b2)  (int8 IMMA) -> f32 H2
    imma_k<2><<<dim3(9, M_PAIR / 64), 256>>>(H1I, saH1, W2I, sbW2, H2, TP, b2p);
    // H2 quantization
    rowmaxH2_k<<<M_PAIR / 8, 256>>>(H2, saH2);
    quant8_k<<<dim3(33, M_PAIR / 64), 256>>>(H2, saH2, H2I);
    // L3: R[b,k] = sum_j relu(H2 @ Wg3 + b3)  (int8 IMMA, fused 8-row sum)
    imma_k<3><<<dim3(9, M_PAIR / 64), 256>>>(H2I, saH2, W3I, sbW3, R, TP, b3p);
    // relations
    relations_k<<<cdiv(NBATCH * TPQ, 256), 256>>>(R, rel);
    // Hf = relu(rel @ Wf1 + bf1)  (bf16 path)
    mmagemm_k<2,0,0,1><<<dim3(9, M_REL / 128), 256, SMB>>>(
        rel, TP, nullptr, Wf1Sp, TP, Hf, TP, nullptr, 0, TP, bf1p);
    fout_k<<<M_REL, 128>>>(Hf, Wf2p, bf2, fo);
    loss_k<<<1, 512>>>(fo, labels, out);
}

// round 9
// speedup vs baseline: 2.5847x; 2.5847x over previous
#include <cuda_runtime.h>
#include <cuda_bf16.h>
#include <cstdint>
#include <math.h>

#define NBATCH  512
#define T       1042
#define TP      1056
#define TPQ     (TP/4)
#define KE      6400
#define KT      528
#define M_EMB   8192
#define M_PAIR  65536
#define M_REL   4096

// ---------------- scratch (device globals; no allocation) ----------------
__device__ __align__(16) float g_P[(size_t)M_EMB * TP];
__device__ __align__(16) float g_Q[(size_t)M_EMB * TP];
__device__ __align__(16) float g_rel[(size_t)M_REL * TP];
__device__ __align__(16) float g_fo[M_REL];
// split (bf16 hi/lo, fragment-permuted) buffers: [tile][kb][limb][1024] u32
__device__ __align__(16) uint32_t g_taggedSp[(size_t)64 * 33 * 2048];
__device__ __align__(16) uint32_t g_H1Sp[(size_t)512 * 66 * 2048];
__device__ __align__(16) uint32_t g_H2Sp[(size_t)512 * 66 * 2048];
__device__ __align__(16) uint32_t g_WembSp[(size_t)4 * 400 * 2048];
__device__ __align__(16) uint32_t g_W1tSp[(size_t)9 * 33 * 2048];
__device__ __align__(16) uint32_t g_W1bSp[(size_t)9 * 33 * 2048];
__device__ __align__(16) uint32_t g_W2Sp[(size_t)9 * 66 * 2048];
__device__ __align__(16) uint32_t g_W3Sp[(size_t)9 * 66 * 2048];
__device__ __align__(16) uint32_t g_Wf1Sp[(size_t)9 * 66 * 2048];
__device__ __align__(16) float g_Wf2p[TP];
__device__ __align__(16) float g_b1[TP];
__device__ __align__(16) float g_b2[TP];
__device__ __align__(16) float g_b3[TP];
__device__ __align__(16) float g_bf1[TP];

// ---------------- helpers -------------------------------------------------
__device__ __forceinline__ void split2(float a, float b, uint32_t& h, uint32_t& l) {
    __nv_bfloat16 ha = __float2bfloat16(a);
    __nv_bfloat16 hb = __float2bfloat16(b);
    float fa = __bfloat162float(ha), fb = __bfloat162float(hb);
    __nv_bfloat16 la = __float2bfloat16(a - fa);
    __nv_bfloat16 lb = __float2bfloat16(b - fb);
    h = (uint32_t)__bfloat16_as_ushort(ha) | ((uint32_t)__bfloat16_as_ushort(hb) << 16);
    l = (uint32_t)__bfloat16_as_ushort(la) | ((uint32_t)__bfloat16_as_ushort(lb) << 16);
}

__device__ __forceinline__ void mma16(float acc[4], const uint32_t a[4], const uint32_t b[2]) {
    asm volatile(
        "mma.sync.aligned.m16n8k16.row.col.f32.bf16.bf16.f32 "
        "{%0,%1,%2,%3},{%4,%5,%6,%7},{%8,%9},{%0,%1,%2,%3};"
        : "+f"(acc[0]), "+f"(acc[1]), "+f"(acc[2]), "+f"(acc[3])
        : "r"(a[0]), "r"(a[1]), "r"(a[2]), "r"(a[3]), "r"(b[0]), "r"(b[1]));
}

__device__ __forceinline__ uint32_t smem_u32(const void* p) {
    uint32_t a;
    asm("{ .reg .u64 t; cvta.to.shared.u64 t, %1; cvt.u32.u64 %0, t; }" : "=r"(a) : "l"(p));
    return a;
}
#define CP16(saddr, gptr) \
    asm volatile("cp.async.cg.shared.global [%0], [%1], 16;" :: "r"(saddr), "l"(gptr))
#define CP4(saddr, gptr) \
    asm volatile("cp.async.ca.shared.global [%0], [%1], 4;" :: "r"(saddr), "l"(gptr))
#define CP_COMMIT() asm volatile("cp.async.commit_group;" ::: "memory")
#define CP_WAIT1()  asm volatile("cp.async.wait_group 1;" ::: "memory")
#define CP_WAIT0()  asm volatile("cp.async.wait_group 0;" ::: "memory")

constexpr int A_HI = 0;
constexpr int A_LO = 1032;
constexpr int B_HI = 2064;
constexpr int B_LO = 3096;
constexpr int STG  = 4128;          // u32 per stage

// ---------------- shared epilogue -----------------------------------------
// EPI: 0 plain store, 1 +bias, 2 +bias+relu  (AOUT selects f32 vs split)
//      4 bias+relu+dot(Wf2) -> atomicAdd fo   (C = fo)
//      5 bias+relu+8row-sum+relations -> rel  (C = rel, ldc = TP)
template<int EPI, int AOUT, int NF>
__device__ __forceinline__ void epilogue(
    float (&acc)[4][NF][4], int Ncols, float* C, int ldc,
    uint32_t* Csp, int KBC, const float* bias, const float* w2v,
    float* smf)
{
    const int t = threadIdx.x;
    const int m0 = blockIdx.y * 128, n0 = blockIdx.x * 128;
    const int L = t & 31, wid = t >> 5, wm = wid >> 2, wn = wid & 3;
    const int baseRow = m0 + wm * 64;

    if (EPI == 4) {
        float pr[4][2];
        #pragma unroll
        for (int mf = 0; mf < 4; mf++) { pr[mf][0] = 0.f; pr[mf][1] = 0.f; }
        #pragma unroll
        for (int mf = 0; mf < 4; mf++) {
            #pragma unroll
            for (int nf = 0; nf < NF; nf++) {
                int col = n0 + wn * 8 * NF + nf * 8 + (L & 3) * 2;
                float2 b2 = *(const float2*)(bias + col);
                float c0 = fmaxf(acc[mf][nf][0] + b2.x, 0.f);
                float c1 = fmaxf(acc[mf][nf][1] + b2.y, 0.f);
                float c2 = fmaxf(acc[mf][nf][2] + b2.x, 0.f);
                float c3 = fmaxf(acc[mf][nf][3] + b2.y, 0.f);
                float2 w = *(const float2*)(w2v + col);
                pr[mf][0] += c0 * w.x + c1 * w.y;
                pr[mf][1] += c2 * w.x + c3 * w.y;
            }
        }
        #pragma unroll
        for (int mf = 0; mf < 4; mf++) {
            pr[mf][0] += __shfl_xor_sync(0xffffffffu, pr[mf][0], 1);
            pr[mf][0] += __shfl_xor_sync(0xffffffffu, pr[mf][0], 2);
            pr[mf][1] += __shfl_xor_sync(0xffffffffu, pr[mf][1], 1);
            pr[mf][1] += __shfl_xor_sync(0xffffffffu, pr[mf][1], 2);
            if ((L & 3) == 0) {
                int row = baseRow + mf * 16 + (L >> 2);
                atomicAdd(C + row, pr[mf][0]);
                atomicAdd(C + row + 8, pr[mf][1]);
            }
        }
        return;
    }

    if (EPI == 5) {
        const int NFC = NF * 32;
        __syncthreads();                    // stages fully consumed before smem reuse
        #pragma unroll
        for (int mf = 0; mf < 4; mf++) {
            #pragma unroll
            for (int nf = 0; nf < NF; nf++) {
                int colL = wn * 8 * NF + nf * 8 + (L & 3) * 2;
                float2 b2 = *(const float2*)(bias + n0 + colL);
                float c0 = fmaxf(acc[mf][nf][0] + b2.x, 0.f);
                float c1 = fmaxf(acc[mf][nf][1] + b2.y, 0.f);
                float c2 = fmaxf(acc[mf][nf][2] + b2.x, 0.f);
                float c3 = fmaxf(acc[mf][nf][3] + b2.y, 0.f);
                c0 += __shfl_down_sync(0xffffffffu, c0, 16);
                c0 += __shfl_down_sync(0xffffffffu, c0, 8);
                c0 += __shfl_down_sync(0xffffffffu, c0, 4);
                c1 += __shfl_down_sync(0xffffffffu, c1, 16);
                c1 += __shfl_down_sync(0xffffffffu, c1, 8);
                c1 += __shfl_down_sync(0xffffffffu, c1, 4);
                c2 += __shfl_down_sync(0xffffffffu, c2, 16);
                c2 += __shfl_down_sync(0xffffffffu, c2, 8);
                c2 += __shfl_down_sync(0xffffffffu, c2, 4);
                c3 += __shfl_down_sync(0xffffffffu, c3, 16);
                c3 += __shfl_down_sync(0xffffffffu, c3, 8);
                c3 += __shfl_down_sync(0xffffffffu, c3, 4);
                if (L < 4) {
                    int gl = (wm * 64 + mf * 16) >> 3;      // 0,2,4,...,14
                    smf[gl * NFC + colL]           = c0;
                    smf[gl * NFC + colL + 1]       = c1;
                    smf[(gl + 1) * NFC + colL]     = c2;
                    smf[(gl + 1) * NFC + colL + 1] = c3;
                }
            }
        }
        __syncthreads();
        const int b = blockIdx.y;
        if (NF == 4) {
            int colL = t & 127, ah = t >> 7;
            float cs = 0.f;
            #pragma unroll
            for (int k = 0; k < 8; k++) cs += smf[k * 128 + colL];
            #pragma unroll
            for (int ai = 0; ai < 4; ai++) {
                int a = ah * 4 + ai;
                C[(size_t)(b * 8 + a) * ldc + n0 + colL] = cs + smf[(8 + a) * 128 + colL];
            }
        } else {
            int colL = t & 31, a = t >> 5;
            float cs = 0.f;
            #pragma unroll
            for (int k = 0; k < 8; k++) cs += smf[k * 32 + colL];
            C[(size_t)(b * 8 + a) * ldc + n0 + colL] = cs + smf[(8 + a) * 32 + colL];
        }
        return;
    }

    if (AOUT == 1) {
        const int mt = blockIdx.y;
        if (NF == 4) {
            #pragma unroll
            for (int mf = 0; mf < 4; mf++) {
                #pragma unroll
                for (int f = 0; f < 2; f++) {
                    int kbC = (n0 >> 4) + wn * 2 + f;
                    if (kbC < KBC) {
                        uint32_t hi[4], lo[4];
                        #pragma unroll
                        for (int s = 0; s < 2; s++) {
                            int nf = 2 * f + s;
                            int col = n0 + wn * 32 + nf * 8 + (L & 3) * 2;
                            float c0 = acc[mf][nf][0], c1 = acc[mf][nf][1];
                            float c2 = acc[mf][nf][2], c3 = acc[mf][nf][3];
                            if (EPI >= 1) {
                                float2 b2 = *(const float2*)(bias + col);
                                c0 += b2.x; c1 += b2.y; c2 += b2.x; c3 += b2.y;
                            }
                            if (EPI >= 2) {
                                c0 = fmaxf(c0, 0.f); c1 = fmaxf(c1, 0.f);
                                c2 = fmaxf(c2, 0.f); c3 = fmaxf(c3, 0.f);
                            }
                            split2(c0, c1, hi[2 * s], lo[2 * s]);
                            split2(c2, c3, hi[2 * s + 1], lo[2 * s + 1]);
                        }
                        size_t base = ((size_t)mt * KBC + kbC) * 2048 + (wm * 4 + mf) * 128 + L * 4;
                        *(uint4*)(Csp + base)        = make_uint4(hi[0], hi[1], hi[2], hi[3]);
                        *(uint4*)(Csp + base + 1024) = make_uint4(lo[0], lo[1], lo[2], lo[3]);
                    }
                }
            }
        } else {
            #pragma unroll
            for (int mf = 0; mf < 4; mf++) {
                int col = n0 + wn * 8 + (L & 3) * 2;
                float c0 = acc[mf][0][0], c1 = acc[mf][0][1];
                float c2 = acc[mf][0][2], c3 = acc[mf][0][3];
                if (EPI >= 1) {
                    float2 b2 = *(const float2*)(bias + col);
                    c0 += b2.x; c1 += b2.y; c2 += b2.x; c3 += b2.y;
                }
                if (EPI >= 2) {
                    c0 = fmaxf(c0, 0.f); c1 = fmaxf(c1, 0.f);
                    c2 = fmaxf(c2, 0.f); c3 = fmaxf(c3, 0.f);
                }
                uint32_t h0, l0, h1, l1;
                split2(c0, c1, h0, l0);
                split2(c2, c3, h1, l1);
                int kbC = (n0 >> 4) + (wn >> 1);
                size_t base = ((size_t)mt * KBC + kbC) * 2048 + (wm * 4 + mf) * 128
                            + L * 4 + 2 * (wn & 1);
                *(uint2*)(Csp + base)        = make_uint2(h0, h1);
                *(uint2*)(Csp + base + 1024) = make_uint2(l0, l1);
            }
        }
        return;
    }

    #pragma unroll
    for (int mf = 0; mf < 4; mf++) {
        #pragma unroll
        for (int nf = 0; nf < NF; nf++) {
            int col = n0 + wn * 8 * NF + nf * 8 + (L & 3) * 2;
            bool cv = col < Ncols;
            float c0 = acc[mf][nf][0], c1 = acc[mf][nf][1];
            float c2 = acc[mf][nf][2], c3 = acc[mf][nf][3];
            if (EPI >= 1) {
                float2 b2 = cv ? *(const float2*)(bias + col) : make_float2(0.f, 0.f);
                c0 += b2.x; c1 += b2.y; c2 += b2.x; c3 += b2.y;
            }
            if (EPI >= 2) {
                c0 = fmaxf(c0, 0.f); c1 = fmaxf(c1, 0.f);
                c2 = fmaxf(c2, 0.f); c3 = fmaxf(c3, 0.f);
            }
            if (cv) {
                int row = baseRow + mf * 16 + (L >> 2);
                *(float2*)(C + (size_t)row * ldc + col)       = make_float2(c0, c1);
                *(float2*)(C + (size_t)(row + 8) * ldc + col) = make_float2(c2, c3);
            }
        }
    }
}

// ---------------- consume one stage (shared by both pipelines) ------------
template<int NF>
__device__ __forceinline__ void consume_stage(
    const uint32_t* stg, float (&acc)[4][NF][4], int L, int wm, int wn)
{
    uint32_t ah[4][4], al[4][4], bh[NF][2], bl[NF][2];
    #pragma unroll
    for (int mf = 0; mf < 4; mf++) {
        const uint32_t* ab = stg + (wm * 4 + mf) * 128 + L * 4;
        *(uint4*)ah[mf] = *(const uint4*)(ab + A_HI);
        *(uint4*)al[mf] = *(const uint4*)(ab + A_LO);
    }
    #pragma unroll
    for (int nf = 0; nf < NF; nf++) {
        const uint32_t* bb = stg + (wn * NF + nf) * 64 + L * 2;
        *(uint2*)bh[nf] = *(const uint2*)(bb + B_HI);
        *(uint2*)bl[nf] = *(const uint2*)(bb + B_LO);
    }
    #pragma unroll
    for (int mf = 0; mf < 4; mf++)
        #pragma unroll
        for (int nf = 0; nf < NF; nf++) {
            mma16(acc[mf][nf], ah[mf], bh[nf]);
            mma16(acc[mf][nf], ah[mf], bl[nf]);
            mma16(acc[mf][nf], al[mf], bh[nf]);
        }
}

// ---------------- reg-pipeline body (A = f32, split on the fly) -----------
template<int EPI, int AOUT, int NF>
__device__ __forceinline__ void gemm_reg(
    const float* __restrict__ A, int lda,
    const uint32_t* __restrict__ Bsp,
    int Ncols, float* __restrict__ C, int ldc,
    uint32_t* __restrict__ Csp, int KBC,
    int K, const float* __restrict__ bias, const float* __restrict__ w2v,
    uint32_t* smu)
{
    const int t  = threadIdx.x;
    const int m0 = blockIdx.y * 128;
    const int KB = K >> 4;
    const int prow = t >> 1, pks = t & 1;
    const int p8 = prow & 7, rb8 = (prow >> 3) & 1, fb = prow >> 4;
    const float* ApA = A + (size_t)(m0 + prow) * lda + pks * 8;

    float va[8];
    uint4 hB, lB;
    const int L = t & 31, wid = t >> 5, wm = wid >> 2, wn = wid & 3;
    float acc[4][NF][4];
    #pragma unroll
    for (int i = 0; i < 4; i++)
        #pragma unroll
        for (int j = 0; j < NF; j++)
            #pragma unroll
            for (int v = 0; v < 4; v++) acc[i][j][v] = 0.f;

    auto ldtile = [&](int kb) {
        const uint32_t* gB = Bsp + ((size_t)(blockIdx.x * KB + kb)) * 2048;
        if (NF == 4) {
            hB = ((const uint4*)gB)[t];
            lB = ((const uint4*)gB)[256 + t];
        } else {
            hB.x = gB[t];
            lB.x = gB[1024 + t];
        }
        int k0 = kb * 16;
        float4 x0 = *(const float4*)(ApA + k0);
        float4 x1 = *(const float4*)(ApA + k0 + 4);
        va[0] = x0.x; va[1] = x0.y; va[2] = x0.z; va[3] = x0.w;
        va[4] = x1.x; va[5] = x1.y; va[6] = x1.z; va[7] = x1.w;
    };
    auto sttile = [&](uint32_t* stg) {
        if (NF == 4) {
            *(uint4*)(stg + B_HI + t * 4) = hB;
            *(uint4*)(stg + B_LO + t * 4) = lB;
        } else {
            stg[B_HI + t] = hB.x;
            stg[B_LO + t] = lB.x;
        }
        #pragma unroll
        for (int j = 0; j < 4; j++) {
            uint32_t h, l;
            split2(va[2 * j], va[2 * j + 1], h, l);
            int ai = fb * 128 + (p8 * 4 + j) * 4 + rb8 + 2 * pks;
            stg[A_HI + ai] = h;
            stg[A_LO + ai] = l;
        }
    };

    ldtile(0);
    sttile(smu);
    __syncthreads();
    for (int kb = 0; kb < KB; kb++) {
        if (kb + 1 < KB) ldtile(kb + 1);
        consume_stage<NF>(smu + (kb & 1) * STG, acc, L, wm, wn);
        if (kb + 1 < KB) sttile(smu + ((kb + 1) & 1) * STG);
        __syncthreads();
    }
    epilogue<EPI, AOUT, NF>(acc, Ncols, C, ldc, Csp, KBC, bias, w2v, (float*)smu);
}

// ---------------- cp.async 3-stage body (A pre-split, pure copy) ----------
template<int EPI, int AOUT, int NF>
__device__ __forceinline__ void gemm_cpa(
    const uint32_t* __restrict__ Asp,
    const uint32_t* __restrict__ Bsp,
    int Ncols, float* __restrict__ C, int ldc,
    uint32_t* __restrict__ Csp, int KBC,
    int K, const float* __restrict__ bias, const float* __restrict__ w2v,
    uint32_t* smu)
{
    const int t  = threadIdx.x;
    const int KB = K >> 4;
    const int L = t & 31, wid = t >> 5, wm = wid >> 2, wn = wid & 3;
    const uint32_t sbase = smem_u32(smu);

    float acc[4][NF][4];
    #pragma unroll
    for (int i = 0; i < 4; i++)
        #pragma unroll
        for (int j = 0; j < NF; j++)
            #pragma unroll
            for (int v = 0; v < 4; v++) acc[i][j][v] = 0.f;

    auto copyasync = [&](int kb, int stage) {
        uint32_t s0 = sbase + (uint32_t)stage * STG * 4;
        const uint32_t* gA = Asp + ((size_t)(blockIdx.y * KB + kb)) * 2048;
        const uint32_t* gB = Bsp + ((size_t)(blockIdx.x * KB + kb)) * 2048;
        CP16(s0 + (A_HI + t * 4) * 4, gA + t * 4);
        CP16(s0 + (A_LO + t * 4) * 4, gA + 1024 + t * 4);
        if (NF == 4) {
            CP16(s0 + (B_HI + t * 4) * 4, gB + t * 4);
            CP16(s0 + (B_LO + t * 4) * 4, gB + 1024 + t * 4);
        } else {
            CP4(s0 + (B_HI + t) * 4, gB + t);
            CP4(s0 + (B_LO + t) * 4, gB + 1024 + t);
        }
        CP_COMMIT();
    };

    copyasync(0, 0);
    copyasync(1, 1);
    int stage = 0;
    for (int kb = 0; kb < KB; kb++) {
        if (kb < KB - 1) CP_WAIT1(); else CP_WAIT0();
        __syncthreads();
        consume_stage<NF>(smu + stage * STG, acc, L, wm, wn);
        if (kb + 2 < KB) {
            int ns = stage + 2;
            if (ns >= 3) ns -= 3;
            copyasync(kb + 2, ns);
        }
        stage = (stage + 1 == 3) ? 0 : stage + 1;
    }
    epilogue<EPI, AOUT, NF>(acc, Ncols, C, ldc, Csp, KBC, bias, w2v, (float*)smu);
}

// ---------------- kernels -------------------------------------------------
template<int EPI, int ASRC, int AOUT, int NARROW>
__global__ void __launch_bounds__(256, 1) mmagemm_k(
    const float* __restrict__ A, int lda,
    const uint32_t* __restrict__ Asp,
    const uint32_t* __restrict__ Bsp,
    int Ncols, float* __restrict__ C, int ldc,
    uint32_t* __restrict__ Csp, int KBC,
    int K, const float* __restrict__ bias, const float* __restrict__ w2v)
{
    extern __shared__ uint32_t smu[];
    if (ASRC == 2) {
        if (NARROW && blockIdx.x == gridDim.x - 1)
            gemm_cpa<EPI, AOUT, 1>(Asp, Bsp, Ncols, C, ldc, Csp, KBC, K, bias, w2v, smu);
        else
            gemm_cpa<EPI, AOUT, 4>(Asp, Bsp, Ncols, C, ldc, Csp, KBC, K, bias, w2v, smu);
    } else {
        if (NARROW && blockIdx.x == gridDim.x - 1)
            gemm_reg<EPI, AOUT, 1>(A, lda, Bsp, Ncols, C, ldc, Csp, KBC, K, bias, w2v, smu);
        else
            gemm_reg<EPI, AOUT, 4>(A, lda, Bsp, Ncols, C, ldc, Csp, KBC, K, bias, w2v, smu);
    }
}

// ============ bf16 weight transpose + split + fragment-permute ============
__global__ void wsplit_k(uint32_t* __restrict__ dst, const float* __restrict__ src,
                         int NT, int KB, int sK, int sN, int sStride, int rowOff)
{
    int idx = blockIdx.x * blockDim.x + threadIdx.x;
    if (idx >= NT * KB * 1024) return;
    int bi  = idx & 1023;
    int pks = bi & 1;
    int lj  = (bi >> 1) & 31;
    int nb  = bi >> 6;
    int p8  = lj >> 2, j = lj & 3;
    int nt  = idx / (KB * 1024);
    int kb  = (idx >> 10) % KB;
    int n = nt * 128 + nb * 8 + p8;
    int k = kb * 16 + pks * 8 + 2 * j;
    float w0 = (k < sK && n < sN)     ? src[(size_t)(k + rowOff) * sStride + n]     : 0.f;
    float w1 = (k + 1 < sK && n < sN) ? src[(size_t)(k + 1 + rowOff) * sStride + n] : 0.f;
    uint32_t h, l;
    split2(w0, w1, h, l);
    size_t base = ((size_t)(idx >> 10)) * 2048 + bi;
    dst[base] = h;
    dst[base + 1024] = l;
}

// ---- tag one-hot into taggedSp kb 32 (cols 512..527) ---------------------
__global__ void tagsplit_k(uint32_t* __restrict__ tsp)
{
    int idx = blockIdx.x * blockDim.x + threadIdx.x;   // 64 * 1024
    if (idx >= 64 * 1024) return;
    int ai = idx & 1023;
    int mt = idx >> 10;
    int w = ai & 127, fbv = ai >> 7;
    int lane = w >> 2, rem = w & 3;
    int rb8 = rem & 1, pks = rem >> 1;
    int p8 = lane >> 2, j = lane & 3;
    int r = mt * 128 + fbv * 16 + rb8 * 8 + p8;
    int col = 512 + pks * 8 + 2 * j;
    int tpos = ((r & 15) < 8) ? (r & 15) : 8;
    int tcol = 512 + tpos;
    uint32_t h = 0;
    if (col == tcol)     h |= 0x3F80u;
    if (col + 1 == tcol) h |= 0x3F80u << 16;
    size_t base = ((size_t)mt * 33 + 32) * 2048 + ai;
    tsp[base] = h;
    tsp[base + 1024] = 0u;
}

// ---- H1 expand + split: relu(P[b,j]+Q[b,k]+b1) -> H1Sp -------------------
__global__ void expandsp_k(const float* __restrict__ P, const float* __restrict__ Q,
                           const float* __restrict__ b1, uint32_t* __restrict__ H1sp)
{
    __shared__ float sP[8][16], sQ[16][16], sB[16];
    int b = blockIdx.y, kb = blockIdx.x;
    int t = threadIdx.x;
    int k0 = kb * 16;
    if (t < 96) {
        int row = t >> 2, q = t & 3;
        const float* src = (row < 8) ? (P + (size_t)(b * 16 + row) * TP)
                                     : (Q + (size_t)(b * 16 + row - 8) * TP);
        float4 v = *(const float4*)(src + k0 + q * 4);
        if (row < 8) *(float4*)&sP[row][q * 4] = v;
        else         *(float4*)&sQ[row - 8][q * 4] = v;
    } else if (t < 100) {
        int q = t - 96;
        *(float4*)&sB[q * 4] = *(const float4*)(b1 + k0 + q * 4);
    }
    __syncthreads();
    int L = t & 31;
    int p8 = L >> 2, j = L & 3;
    int fbv = t >> 5;
    uint32_t hi[4], lo[4];
    #pragma unroll
    for (int s = 0; s < 2; s++) {
        int kA = s * 8 + 2 * j;
        #pragma unroll
        for (int rb = 0; rb < 2; rb++) {
            int r = fbv * 16 + rb * 8 + p8;
            int jj = r & 7, kk = r >> 3;
            float e0 = fmaxf(sP[jj][kA]     + sQ[kk][kA]     + sB[kA],     0.f);
            float e1 = fmaxf(sP[jj][kA + 1] + sQ[kk][kA + 1] + sB[kA + 1], 0.f);
            split2(e0, e1, hi[2 * s + rb], lo[2 * s + rb]);
        }
    }
    size_t base = ((size_t)b * 66 + kb) * 2048 + t * 4;
    *(uint4*)(H1sp + base)        = make_uint4(hi[0], hi[1], hi[2], hi[3]);
    *(uint4*)(H1sp + base + 1024) = make_uint4(lo[0], lo[1], lo[2], lo[3]);
}

// ======================= small kernels ====================================
__global__ void pad2d_k(float* __restrict__ dst, const float* __restrict__ src,
                        int dR, int dC, int sR, int sC, int sStride, int sRowOff)
{
    int idx = blockIdx.x * blockDim.x + threadIdx.x;
    if (idx >= dR * dC) return;
    int r = idx / dC, c = idx % dC;
    float v = 0.f;
    if (r < sR && c < sC) v = src[(size_t)(r + sRowOff) * sStride + c];
    dst[idx] = v;
}

__inline__ __device__ float warp_sum(float v)
{
    #pragma unroll
    for (int o = 16; o; o >>= 1) v += __shfl_down_sync(0xffffffffu, v, o);
    return v;
}

__global__ void loss_k(const float* __restrict__ fo, const int* __restrict__ labels,
                       const float* __restrict__ bf2, float* __restrict__ out)
{
    int b = threadIdx.x;
    int lab = labels[b];
    float bias2 = bf2[0];
    float lsum = 0.f;
    float best = -1e30f; int bi = 0;
    #pragma unroll
    for (int a = 0; a < 8; a++) {
        float f = fo[b * 8 + a] + bias2;
        float l = fmaxf(f, 0.f) - f * ((a == lab) ? 1.f : 0.f) + log1pf(expf(-fabsf(f)));
        lsum += l;
        if (f > best) { best = f; bi = a; }
    }
    float cor = (bi == lab) ? 1.f : 0.f;
    lsum = warp_sum(lsum);
    cor  = warp_sum(cor);
    __shared__ float sl[16], sc[16];
    int wid = threadIdx.x >> 5, lane = threadIdx.x & 31;
    if (lane == 0) { sl[wid] = lsum; sc[wid] = cor; }
    __syncthreads();
    if (wid == 0) {
        float a = (lane < 16) ? sl[lane] : 0.f;
        float c = (lane < 16) ? sc[lane] : 0.f;
        a = warp_sum(a);
        c = warp_sum(c);
        if (lane == 0) {
            out[0] = a / (float)(NBATCH * 8);
            out[1] = c / (float)NBATCH;
        }
    }
}

// ======================= host =============================================
static inline int cdiv(int a, int b) { return (a + b - 1) / b; }

extern "C" void kernel_launch(void* const* d_in, const int* in_sizes, int n_in,
                              void* d_out, int out_size)
{
    const float* x      = (const float*)d_in[0];
    const float* W_emb  = (const float*)d_in[1];
    const float* b_emb  = (const float*)d_in[2];
    const float* Wg1    = (const float*)d_in[3];
    const float* bg1    = (const float*)d_in[4];
    const float* Wg2    = (const float*)d_in[5];
    const float* bg2    = (const float*)d_in[6];
    const float* Wg3    = (const float*)d_in[7];
    const float* bg3    = (const float*)d_in[8];
    const float* Wf1    = (const float*)d_in[9];
    const float* bf1    = (const float*)d_in[10];
    const float* Wf2    = (const float*)d_in[11];
    const float* bf2    = (const float*)d_in[12];
    const int*   labels = (const int*)d_in[13];
    float* out = (float*)d_out;

    float *P, *Q, *rel, *fo;
    float *Wf2p, *b1p, *b2p, *b3p, *bf1p;
    uint32_t *taggedSp, *H1Sp, *H2Sp, *WembSp, *W1tSp, *W1bSp, *W2Sp, *W3Sp, *Wf1Sp;
    cudaGetSymbolAddress((void**)&P, g_P);
    cudaGetSymbolAddress((void**)&Q, g_Q);
    cudaGetSymbolAddress((void**)&rel, g_rel);
    cudaGetSymbolAddress((void**)&fo, g_fo);
    cudaGetSymbolAddress((void**)&taggedSp, g_taggedSp);
    cudaGetSymbolAddress((void**)&H1Sp, g_H1Sp);
    cudaGetSymbolAddress((void**)&H2Sp, g_H2Sp);
    cudaGetSymbolAddress((void**)&WembSp, g_WembSp);
    cudaGetSymbolAddress((void**)&W1tSp, g_W1tSp);
    cudaGetSymbolAddress((void**)&W1bSp, g_W1bSp);
    cudaGetSymbolAddress((void**)&W2Sp, g_W2Sp);
    cudaGetSymbolAddress((void**)&W3Sp, g_W3Sp);
    cudaGetSymbolAddress((void**)&Wf1Sp, g_Wf1Sp);
    cudaGetSymbolAddress((void**)&Wf2p, g_Wf2p);
    cudaGetSymbolAddress((void**)&b1p, g_b1);
    cudaGetSymbolAddress((void**)&b2p, g_b2);
    cudaGetSymbolAddress((void**)&b3p, g_b3);
    cudaGetSymbolAddress((void**)&bf1p, g_bf1);

    const int SMB2 = 2 * STG * 4;   // 33024 bytes (reg pipeline)
    const int SMB3 = 3 * STG * 4;   // 49536 bytes (cp.async pipeline)
    cudaFuncSetAttribute(mmagemm_k<1,0,1,0>, cudaFuncAttributeMaxDynamicSharedMemorySize, SMB2);
    cudaFuncSetAttribute(mmagemm_k<0,2,0,1>, cudaFuncAttributeMaxDynamicSharedMemorySize, SMB3);
    cudaFuncSetAttribute(mmagemm_k<2,2,1,1>, cudaFuncAttributeMaxDynamicSharedMemorySize, SMB3);
    cudaFuncSetAttribute(mmagemm_k<5,2,0,1>, cudaFuncAttributeMaxDynamicSharedMemorySize, SMB3);
    cudaFuncSetAttribute(mmagemm_k<4,0,0,1>, cudaFuncAttributeMaxDynamicSharedMemorySize, SMB2);

    // ---- one-time weight prep ----
    wsplit_k<<<cdiv(4 * 400 * 1024, 256), 256>>>(WembSp, W_emb, 4, 400, KE, 512, 512, 0);
    wsplit_k<<<cdiv(9 * 33 * 1024, 256), 256>>>(W1tSp, Wg1, 9, 33, 521, T, T, 0);
    wsplit_k<<<cdiv(9 * 33 * 1024, 256), 256>>>(W1bSp, Wg1, 9, 33, 521, T, T, 521);
    wsplit_k<<<cdiv(9 * 66 * 1024, 256), 256>>>(W2Sp,  Wg2, 9, 66, T, T, T, 0);
    wsplit_k<<<cdiv(9 * 66 * 1024, 256), 256>>>(W3Sp,  Wg3, 9, 66, T, T, T, 0);
    wsplit_k<<<cdiv(9 * 66 * 1024, 256), 256>>>(Wf1Sp, Wf1, 9, 66, T, T, T, 0);
    pad2d_k<<<cdiv(TP, 256), 256>>>(Wf2p, Wf2, 1, TP, 1, T, T, 0);
    pad2d_k<<<cdiv(TP, 256), 256>>>(b1p, bg1, 1, TP, 1, T, T, 0);
    pad2d_k<<<cdiv(TP, 256), 256>>>(b2p, bg2, 1, TP, 1, T, T, 0);
    pad2d_k<<<cdiv(TP, 256), 256>>>(b3p, bg3, 1, TP, 1, T, T, 0);
    pad2d_k<<<cdiv(TP, 256), 256>>>(bf1p, bf1, 1, TP, 1, T, T, 0);
    tagsplit_k<<<cdiv(64 * 1024, 256), 256>>>(taggedSp);
    cudaMemsetAsync(fo, 0, M_REL * sizeof(float));

    // emb = x @ W_emb + b_emb -> taggedSp (split layout, kb 0..31; kb 32 = tags)
    mmagemm_k<1,0,1,0><<<dim3(4, M_EMB / 128), 256, SMB2>>>(
        x, KE, nullptr, WembSp, 512, nullptr, 0, taggedSp, 33, KE, b_emb, nullptr);
    // P = tagged @ Wg1_top ; Q = tagged @ Wg1_bot  (cp.async, narrow 9th tile)
    mmagemm_k<0,2,0,1><<<dim3(9, M_EMB / 128), 256, SMB3>>>(
        nullptr, 0, taggedSp, W1tSp, TP, P, TP, nullptr, 0, KT, nullptr, nullptr);
    mmagemm_k<0,2,0,1><<<dim3(9, M_EMB / 128), 256, SMB3>>>(
        nullptr, 0, taggedSp, W1bSp, TP, Q, TP, nullptr, 0, KT, nullptr, nullptr);
    // H1 = relu(P[j]+Q[k]+b1), split once into H1Sp
    expandsp_k<<<dim3(66, NBATCH), 256>>>(P, Q, b1p, H1Sp);
    // L2: H2 = relu(H1 @ Wg2 + b2) -> H2Sp (split layout)
    mmagemm_k<2,2,1,1><<<dim3(9, M_PAIR / 128), 256, SMB3>>>(
        nullptr, 0, H1Sp, W2Sp, TP, nullptr, 0, H2Sp, 66, TP, b2p, nullptr);
    // L3: relations fused — 8-row sums + cross-k combine -> rel
    mmagemm_k<5,2,0,1><<<dim3(9, M_PAIR / 128), 256, SMB3>>>(
        nullptr, 0, H2Sp, W3Sp, TP, rel, TP, nullptr, 0, TP, b3p, nullptr);
    // f: Hf = relu(rel @ Wf1 + bf1); f_out partial-dot fused via atomics -> fo
    mmagemm_k<4,0,0,1><<<dim3(9, M_REL / 128), 256, SMB2>>>(
        rel, TP, nullptr, Wf1Sp, TP, fo, TP, nullptr, 0, TP, bf1p, Wf2p);
    loss_k<<<1, 512>>>(fo, labels, bf2, out);
}

// round 10
// speedup vs baseline: 2.6945x; 1.0425x over previous
#include <cuda_runtime.h>
#include <cuda_bf16.h>
#include <cstdint>
#include <math.h>

#define NBATCH  512
#define T       1042
#define TP      1056
#define TPQ     (TP/4)
#define KE      6400
#define KT      528
#define M_EMB   8192
#define M_PAIR  65536
#define M_REL   4096

// ---------------- scratch (device globals; no allocation) ----------------
__device__ __align__(16) float g_P[(size_t)M_EMB * TP];
__device__ __align__(16) float g_Q[(size_t)M_EMB * TP];
__device__ __align__(16) float g_rel[(size_t)M_REL * TP];
__device__ __align__(16) float g_fo[M_REL];
// split (bf16 hi/lo, fragment-permuted) buffers: [tile][kb][limb][1024] u32
__device__ __align__(16) uint32_t g_xSp[(size_t)64 * 400 * 2048];
__device__ __align__(16) uint32_t g_taggedSp[(size_t)64 * 33 * 2048];
__device__ __align__(16) uint32_t g_H1Sp[(size_t)512 * 66 * 2048];
__device__ __align__(16) uint32_t g_H2Sp[(size_t)512 * 66 * 2048];
__device__ __align__(16) uint32_t g_WembSp[(size_t)4 * 400 * 2048];
__device__ __align__(16) uint32_t g_W1tSp[(size_t)9 * 33 * 2048];
__device__ __align__(16) uint32_t g_W1bSp[(size_t)9 * 33 * 2048];
__device__ __align__(16) uint32_t g_W2Sp[(size_t)9 * 66 * 2048];
__device__ __align__(16) uint32_t g_W3Sp[(size_t)9 * 66 * 2048];
__device__ __align__(16) uint32_t g_Wf1Sp[(size_t)9 * 66 * 2048];
__device__ __align__(16) float g_Wf2p[TP];
__device__ __align__(16) float g_b1[TP];
__device__ __align__(16) float g_b2[TP];
__device__ __align__(16) float g_b3[TP];
__device__ __align__(16) float g_bf1[TP];

// ---------------- helpers -------------------------------------------------
__device__ __forceinline__ void split2(float a, float b, uint32_t& h, uint32_t& l) {
    __nv_bfloat16 ha = __float2bfloat16(a);
    __nv_bfloat16 hb = __float2bfloat16(b);
    float fa = __bfloat162float(ha), fb = __bfloat162float(hb);
    __nv_bfloat16 la = __float2bfloat16(a - fa);
    __nv_bfloat16 lb = __float2bfloat16(b - fb);
    h = (uint32_t)__bfloat16_as_ushort(ha) | ((uint32_t)__bfloat16_as_ushort(hb) << 16);
    l = (uint32_t)__bfloat16_as_ushort(la) | ((uint32_t)__bfloat16_as_ushort(lb) << 16);
}

__device__ __forceinline__ void mma16(float acc[4], const uint32_t a[4], const uint32_t b[2]) {
    asm volatile(
        "mma.sync.aligned.m16n8k16.row.col.f32.bf16.bf16.f32 "
        "{%0,%1,%2,%3},{%4,%5,%6,%7},{%8,%9},{%0,%1,%2,%3};"
        : "+f"(acc[0]), "+f"(acc[1]), "+f"(acc[2]), "+f"(acc[3])
        : "r"(a[0]), "r"(a[1]), "r"(a[2]), "r"(a[3]), "r"(b[0]), "r"(b[1]));
}

__device__ __forceinline__ uint32_t smem_u32(const void* p) {
    uint32_t a;
    asm("{ .reg .u64 t; cvta.to.shared.u64 t, %1; cvt.u32.u64 %0, t; }" : "=r"(a) : "l"(p));
    return a;
}
#define CP16(saddr, gptr) \
    asm volatile("cp.async.cg.shared.global [%0], [%1], 16;" :: "r"(saddr), "l"(gptr))
#define CP4(saddr, gptr) \
    asm volatile("cp.async.ca.shared.global [%0], [%1], 4;" :: "r"(saddr), "l"(gptr))
#define CP_COMMIT() asm volatile("cp.async.commit_group;" ::: "memory")
#define CP_WAIT1()  asm volatile("cp.async.wait_group 1;" ::: "memory")
#define CP_WAIT0()  asm volatile("cp.async.wait_group 0;" ::: "memory")

constexpr int A_HI = 0;
constexpr int A_LO = 1032;
constexpr int B_HI = 2064;
constexpr int B_LO = 3096;
constexpr int STG  = 4128;          // u32 per stage

// ---------------- shared epilogue -----------------------------------------
// EPI: 0 plain store, 1 +bias, 2 +bias+relu  (AOUT selects f32 vs split)
//      4 bias+relu+dot(Wf2) -> atomicAdd fo   (C = fo)
//      5 bias+relu+8row-sum+relations -> rel  (C = rel, ldc = TP)
template<int EPI, int AOUT, int NF>
__device__ __forceinline__ void epilogue(
    float (&acc)[4][NF][4], int Ncols, float* C, int ldc,
    uint32_t* Csp, int KBC, const float* bias, const float* w2v,
    float* smf)
{
    const int t = threadIdx.x;
    const int m0 = blockIdx.y * 128, n0 = blockIdx.x * 128;
    const int L = t & 31, wid = t >> 5, wm = wid >> 2, wn = wid & 3;
    const int baseRow = m0 + wm * 64;

    if (EPI == 4) {
        float pr[4][2];
        #pragma unroll
        for (int mf = 0; mf < 4; mf++) { pr[mf][0] = 0.f; pr[mf][1] = 0.f; }
        #pragma unroll
        for (int mf = 0; mf < 4; mf++) {
            #pragma unroll
            for (int nf = 0; nf < NF; nf++) {
                int col = n0 + wn * 8 * NF + nf * 8 + (L & 3) * 2;
                float2 b2 = *(const float2*)(bias + col);
                float c0 = fmaxf(acc[mf][nf][0] + b2.x, 0.f);
                float c1 = fmaxf(acc[mf][nf][1] + b2.y, 0.f);
                float c2 = fmaxf(acc[mf][nf][2] + b2.x, 0.f);
                float c3 = fmaxf(acc[mf][nf][3] + b2.y, 0.f);
                float2 w = *(const float2*)(w2v + col);
                pr[mf][0] += c0 * w.x + c1 * w.y;
                pr[mf][1] += c2 * w.x + c3 * w.y;
            }
        }
        #pragma unroll
        for (int mf = 0; mf < 4; mf++) {
            pr[mf][0] += __shfl_xor_sync(0xffffffffu, pr[mf][0], 1);
            pr[mf][0] += __shfl_xor_sync(0xffffffffu, pr[mf][0], 2);
            pr[mf][1] += __shfl_xor_sync(0xffffffffu, pr[mf][1], 1);
            pr[mf][1] += __shfl_xor_sync(0xffffffffu, pr[mf][1], 2);
            if ((L & 3) == 0) {
                int row = baseRow + mf * 16 + (L >> 2);
                atomicAdd(C + row, pr[mf][0]);
                atomicAdd(C + row + 8, pr[mf][1]);
            }
        }
        return;
    }

    if (EPI == 5) {
        const int NFC = NF * 32;
        __syncthreads();                    // stages fully consumed before smem reuse
        #pragma unroll
        for (int mf = 0; mf < 4; mf++) {
            #pragma unroll
            for (int nf = 0; nf < NF; nf++) {
                int colL = wn * 8 * NF + nf * 8 + (L & 3) * 2;
                float2 b2 = *(const float2*)(bias + n0 + colL);
                float c0 = fmaxf(acc[mf][nf][0] + b2.x, 0.f);
                float c1 = fmaxf(acc[mf][nf][1] + b2.y, 0.f);
                float c2 = fmaxf(acc[mf][nf][2] + b2.x, 0.f);
                float c3 = fmaxf(acc[mf][nf][3] + b2.y, 0.f);
                c0 += __shfl_down_sync(0xffffffffu, c0, 16);
                c0 += __shfl_down_sync(0xffffffffu, c0, 8);
                c0 += __shfl_down_sync(0xffffffffu, c0, 4);
                c1 += __shfl_down_sync(0xffffffffu, c1, 16);
                c1 += __shfl_down_sync(0xffffffffu, c1, 8);
                c1 += __shfl_down_sync(0xffffffffu, c1, 4);
                c2 += __shfl_down_sync(0xffffffffu, c2, 16);
                c2 += __shfl_down_sync(0xffffffffu, c2, 8);
                c2 += __shfl_down_sync(0xffffffffu, c2, 4);
                c3 += __shfl_down_sync(0xffffffffu, c3, 16);
                c3 += __shfl_down_sync(0xffffffffu, c3, 8);
                c3 += __shfl_down_sync(0xffffffffu, c3, 4);
                if (L < 4) {
                    int gl = (wm * 64 + mf * 16) >> 3;      // 0,2,4,...,14
                    smf[gl * NFC + colL]           = c0;
                    smf[gl * NFC + colL + 1]       = c1;
                    smf[(gl + 1) * NFC + colL]     = c2;
                    smf[(gl + 1) * NFC + colL + 1] = c3;
                }
            }
        }
        __syncthreads();
        const int b = blockIdx.y;
        if (NF == 4) {
            int colL = t & 127, ah = t >> 7;
            float cs = 0.f;
            #pragma unroll
            for (int k = 0; k < 8; k++) cs += smf[k * 128 + colL];
            #pragma unroll
            for (int ai = 0; ai < 4; ai++) {
                int a = ah * 4 + ai;
                C[(size_t)(b * 8 + a) * ldc + n0 + colL] = cs + smf[(8 + a) * 128 + colL];
            }
        } else {
            int colL = t & 31, a = t >> 5;
            float cs = 0.f;
            #pragma unroll
            for (int k = 0; k < 8; k++) cs += smf[k * 32 + colL];
            C[(size_t)(b * 8 + a) * ldc + n0 + colL] = cs + smf[(8 + a) * 32 + colL];
        }
        return;
    }

    if (AOUT == 1) {
        const int mt = blockIdx.y;
        if (NF == 4) {
            #pragma unroll
            for (int mf = 0; mf < 4; mf++) {
                #pragma unroll
                for (int f = 0; f < 2; f++) {
                    int kbC = (n0 >> 4) + wn * 2 + f;
                    if (kbC < KBC) {
                        uint32_t hi[4], lo[4];
                        #pragma unroll
                        for (int s = 0; s < 2; s++) {
                            int nf = 2 * f + s;
                            int col = n0 + wn * 32 + nf * 8 + (L & 3) * 2;
                            float c0 = acc[mf][nf][0], c1 = acc[mf][nf][1];
                            float c2 = acc[mf][nf][2], c3 = acc[mf][nf][3];
                            if (EPI >= 1) {
                                float2 b2 = *(const float2*)(bias + col);
                                c0 += b2.x; c1 += b2.y; c2 += b2.x; c3 += b2.y;
                            }
                            if (EPI >= 2) {
                                c0 = fmaxf(c0, 0.f); c1 = fmaxf(c1, 0.f);
                                c2 = fmaxf(c2, 0.f); c3 = fmaxf(c3, 0.f);
                            }
                            split2(c0, c1, hi[2 * s], lo[2 * s]);
                            split2(c2, c3, hi[2 * s + 1], lo[2 * s + 1]);
                        }
                        size_t base = ((size_t)mt * KBC + kbC) * 2048 + (wm * 4 + mf) * 128 + L * 4;
                        *(uint4*)(Csp + base)        = make_uint4(hi[0], hi[1], hi[2], hi[3]);
                        *(uint4*)(Csp + base + 1024) = make_uint4(lo[0], lo[1], lo[2], lo[3]);
                    }
                }
            }
        } else {
            #pragma unroll
            for (int mf = 0; mf < 4; mf++) {
                int col = n0 + wn * 8 + (L & 3) * 2;
                float c0 = acc[mf][0][0], c1 = acc[mf][0][1];
                float c2 = acc[mf][0][2], c3 = acc[mf][0][3];
                if (EPI >= 1) {
                    float2 b2 = *(const float2*)(bias + col);
                    c0 += b2.x; c1 += b2.y; c2 += b2.x; c3 += b2.y;
                }
                if (EPI >= 2) {
                    c0 = fmaxf(c0, 0.f); c1 = fmaxf(c1, 0.f);
                    c2 = fmaxf(c2, 0.f); c3 = fmaxf(c3, 0.f);
                }
                uint32_t h0, l0, h1, l1;
                split2(c0, c1, h0, l0);
                split2(c2, c3, h1, l1);
                int kbC = (n0 >> 4) + (wn >> 1);
                size_t base = ((size_t)mt * KBC + kbC) * 2048 + (wm * 4 + mf) * 128
                            + L * 4 + 2 * (wn & 1);
                *(uint2*)(Csp + base)        = make_uint2(h0, h1);
                *(uint2*)(Csp + base + 1024) = make_uint2(l0, l1);
            }
        }
        return;
    }

    #pragma unroll
    for (int mf = 0; mf < 4; mf++) {
        #pragma unroll
        for (int nf = 0; nf < NF; nf++) {
            int col = n0 + wn * 8 * NF + nf * 8 + (L & 3) * 2;
            bool cv = col < Ncols;
            float c0 = acc[mf][nf][0], c1 = acc[mf][nf][1];
            float c2 = acc[mf][nf][2], c3 = acc[mf][nf][3];
            if (EPI >= 1) {
                float2 b2 = cv ? *(const float2*)(bias + col) : make_float2(0.f, 0.f);
                c0 += b2.x; c1 += b2.y; c2 += b2.x; c3 += b2.y;
            }
            if (EPI >= 2) {
                c0 = fmaxf(c0, 0.f); c1 = fmaxf(c1, 0.f);
                c2 = fmaxf(c2, 0.f); c3 = fmaxf(c3, 0.f);
            }
            if (cv) {
                int row = baseRow + mf * 16 + (L >> 2);
                *(float2*)(C + (size_t)row * ldc + col)       = make_float2(c0, c1);
                *(float2*)(C + (size_t)(row + 8) * ldc + col) = make_float2(c2, c3);
            }
        }
    }
}

// ---------------- consume one stage ---------------------------------------
template<int NF>
__device__ __forceinline__ void consume_stage(
    const uint32_t* stg, float (&acc)[4][NF][4], int L, int wm, int wn)
{
    uint32_t ah[4][4], al[4][4], bh[NF][2], bl[NF][2];
    #pragma unroll
    for (int mf = 0; mf < 4; mf++) {
        const uint32_t* ab = stg + (wm * 4 + mf) * 128 + L * 4;
        *(uint4*)ah[mf] = *(const uint4*)(ab + A_HI);
        *(uint4*)al[mf] = *(const uint4*)(ab + A_LO);
    }
    #pragma unroll
    for (int nf = 0; nf < NF; nf++) {
        const uint32_t* bb = stg + (wn * NF + nf) * 64 + L * 2;
        *(uint2*)bh[nf] = *(const uint2*)(bb + B_HI);
        *(uint2*)bl[nf] = *(const uint2*)(bb + B_LO);
    }
    #pragma unroll
    for (int mf = 0; mf < 4; mf++)
        #pragma unroll
        for (int nf = 0; nf < NF; nf++) {
            mma16(acc[mf][nf], ah[mf], bh[nf]);
            mma16(acc[mf][nf], ah[mf], bl[nf]);
            mma16(acc[mf][nf], al[mf], bh[nf]);
        }
}

// ---------------- reg-pipeline body (A = f32, split on the fly) -----------
template<int EPI, int AOUT, int NF>
__device__ __forceinline__ void gemm_reg(
    const float* __restrict__ A, int lda,
    const uint32_t* __restrict__ Bsp,
    int Ncols, float* __restrict__ C, int ldc,
    uint32_t* __restrict__ Csp, int KBC,
    int K, const float* __restrict__ bias, const float* __restrict__ w2v,
    uint32_t* smu)
{
    const int t  = threadIdx.x;
    const int m0 = blockIdx.y * 128;
    const int KB = K >> 4;
    const int prow = t >> 1, pks = t & 1;
    const int p8 = prow & 7, rb8 = (prow >> 3) & 1, fb = prow >> 4;
    const float* ApA = A + (size_t)(m0 + prow) * lda + pks * 8;

    float va[8];
    uint4 hB, lB;
    const int L = t & 31, wid = t >> 5, wm = wid >> 2, wn = wid & 3;
    float acc[4][NF][4];
    #pragma unroll
    for (int i = 0; i < 4; i++)
        #pragma unroll
        for (int j = 0; j < NF; j++)
            #pragma unroll
            for (int v = 0; v < 4; v++) acc[i][j][v] = 0.f;

    auto ldtile = [&](int kb) {
        const uint32_t* gB = Bsp + ((size_t)(blockIdx.x * KB + kb)) * 2048;
        if (NF == 4) {
            hB = ((const uint4*)gB)[t];
            lB = ((const uint4*)gB)[256 + t];
        } else {
            hB.x = gB[t];
            lB.x = gB[1024 + t];
        }
        int k0 = kb * 16;
        float4 x0 = *(const float4*)(ApA + k0);
        float4 x1 = *(const float4*)(ApA + k0 + 4);
        va[0] = x0.x; va[1] = x0.y; va[2] = x0.z; va[3] = x0.w;
        va[4] = x1.x; va[5] = x1.y; va[6] = x1.z; va[7] = x1.w;
    };
    auto sttile = [&](uint32_t* stg) {
        if (NF == 4) {
            *(uint4*)(stg + B_HI + t * 4) = hB;
            *(uint4*)(stg + B_LO + t * 4) = lB;
        } else {
            stg[B_HI + t] = hB.x;
            stg[B_LO + t] = lB.x;
        }
        #pragma unroll
        for (int j = 0; j < 4; j++) {
            uint32_t h, l;
            split2(va[2 * j], va[2 * j + 1], h, l);
            int ai = fb * 128 + (p8 * 4 + j) * 4 + rb8 + 2 * pks;
            stg[A_HI + ai] = h;
            stg[A_LO + ai] = l;
        }
    };

    ldtile(0);
    sttile(smu);
    __syncthreads();
    for (int kb = 0; kb < KB; kb++) {
        if (kb + 1 < KB) ldtile(kb + 1);
        consume_stage<NF>(smu + (kb & 1) * STG, acc, L, wm, wn);
        if (kb + 1 < KB) sttile(smu + ((kb + 1) & 1) * STG);
        __syncthreads();
    }
    epilogue<EPI, AOUT, NF>(acc, Ncols, C, ldc, Csp, KBC, bias, w2v, (float*)smu);
}

// ---------------- cp.async 3-stage body (A pre-split, pure copy) ----------
template<int EPI, int AOUT, int NF>
__device__ __forceinline__ void gemm_cpa(
    const uint32_t* __restrict__ Asp,
    const uint32_t* __restrict__ Bsp,
    int Ncols, float* __restrict__ C, int ldc,
    uint32_t* __restrict__ Csp, int KBC,
    int K, const float* __restrict__ bias, const float* __restrict__ w2v,
    uint32_t* smu)
{
    const int t  = threadIdx.x;
    const int KB = K >> 4;
    const int L = t & 31, wid = t >> 5, wm = wid >> 2, wn = wid & 3;
    const uint32_t sbase = smem_u32(smu);

    float acc[4][NF][4];
    #pragma unroll
    for (int i = 0; i < 4; i++)
        #pragma unroll
        for (int j = 0; j < NF; j++)
            #pragma unroll
            for (int v = 0; v < 4; v++) acc[i][j][v] = 0.f;

    auto copyasync = [&](int kb, int stage) {
        uint32_t s0 = sbase + (uint32_t)stage * STG * 4;
        const uint32_t* gA = Asp + ((size_t)(blockIdx.y * KB + kb)) * 2048;
        const uint32_t* gB = Bsp + ((size_t)(blockIdx.x * KB + kb)) * 2048;
        CP16(s0 + (A_HI + t * 4) * 4, gA + t * 4);
        CP16(s0 + (A_LO + t * 4) * 4, gA + 1024 + t * 4);
        if (NF == 4) {
            CP16(s0 + (B_HI + t * 4) * 4, gB + t * 4);
            CP16(s0 + (B_LO + t * 4) * 4, gB + 1024 + t * 4);
        } else {
            CP4(s0 + (B_HI + t) * 4, gB + t);
            CP4(s0 + (B_LO + t) * 4, gB + 1024 + t);
        }
        CP_COMMIT();
    };

    copyasync(0, 0);
    copyasync(1, 1);
    int stage = 0;
    for (int kb = 0; kb < KB; kb++) {
        if (kb < KB - 1) CP_WAIT1(); else CP_WAIT0();
        __syncthreads();
        consume_stage<NF>(smu + stage * STG, acc, L, wm, wn);
        if (kb + 2 < KB) {
            int ns = stage + 2;
            if (ns >= 3) ns -= 3;
            copyasync(kb + 2, ns);
        }
        stage = (stage + 1 == 3) ? 0 : stage + 1;
    }
    epilogue<EPI, AOUT, NF>(acc, Ncols, C, ldc, Csp, KBC, bias, w2v, (float*)smu);
}

// ---------------- kernels -------------------------------------------------
template<int EPI, int ASRC, int AOUT, int NARROW>
__global__ void __launch_bounds__(256, 1) mmagemm_k(
    const float* __restrict__ A, int lda,
    const uint32_t* __restrict__ Asp,
    const uint32_t* __restrict__ Bsp,
    int Ncols, float* __restrict__ C, int ldc,
    uint32_t* __restrict__ Csp, int KBC,
    int K, const float* __restrict__ bias, const float* __restrict__ w2v)
{
    extern __shared__ uint32_t smu[];
    if (ASRC == 2) {
        if (NARROW && blockIdx.x == gridDim.x - 1)
            gemm_cpa<EPI, AOUT, 1>(Asp, Bsp, Ncols, C, ldc, Csp, KBC, K, bias, w2v, smu);
        else
            gemm_cpa<EPI, AOUT, 4>(Asp, Bsp, Ncols, C, ldc, Csp, KBC, K, bias, w2v, smu);
    } else {
        if (NARROW && blockIdx.x == gridDim.x - 1)
            gemm_reg<EPI, AOUT, 1>(A, lda, Bsp, Ncols, C, ldc, Csp, KBC, K, bias, w2v, smu);
        else
            gemm_reg<EPI, AOUT, 4>(A, lda, Bsp, Ncols, C, ldc, Csp, KBC, K, bias, w2v, smu);
    }
}

// ---------------- x pre-split: f32 -> A-fragment split layout -------------
// dst [mt 0..63][kb 0..399]: 1024 u32 hi + 1024 u32 lo.
__global__ void xsplit_k(uint32_t* __restrict__ dst, const float* __restrict__ src)
{
    const int mt = blockIdx.y;
    const int t = threadIdx.x;
    const int prow = t >> 1, pks = t & 1;
    const int p8 = prow & 7, rb8 = (prow >> 3) & 1, fb = prow >> 4;
    const float* A = src + (size_t)(mt * 128 + prow) * KE + pks * 8;
    const int kb0 = blockIdx.x * 8;
    #pragma unroll 2
    for (int kb = kb0; kb < kb0 + 8; kb++) {
        float4 x0 = *(const float4*)(A + kb * 16);
        float4 x1 = *(const float4*)(A + kb * 16 + 4);
        float va[8] = {x0.x, x0.y, x0.z, x0.w, x1.x, x1.y, x1.z, x1.w};
        uint32_t* stg = dst + ((size_t)mt * 400 + kb) * 2048;
        #pragma unroll
        for (int j = 0; j < 4; j++) {
            uint32_t h, l;
            split2(va[2 * j], va[2 * j + 1], h, l);
            int ai = fb * 128 + (p8 * 4 + j) * 4 + rb8 + 2 * pks;
            stg[ai] = h;
            stg[1024 + ai] = l;
        }
    }
}

// ---------------- merged prep: all weight splits + tags + bias pads -------
__device__ __forceinline__ void wsplit_body(
    uint32_t* dst, const float* src, int idx,
    int KB, int sK, int sN, int sStride, int rowOff)
{
    int bi  = idx & 1023;
    int pks = bi & 1;
    int lj  = (bi >> 1) & 31;
    int nb  = bi >> 6;
    int p8  = lj >> 2, j = lj & 3;
    int tile = idx >> 10;
    int nt = tile / KB, kb = tile % KB;
    int n = nt * 128 + nb * 8 + p8;
    int k = kb * 16 + pks * 8 + 2 * j;
    float w0 = (k < sK && n < sN)     ? src[(size_t)(k + rowOff) * sStride + n]     : 0.f;
    float w1 = (k + 1 < sK && n < sN) ? src[(size_t)(k + 1 + rowOff) * sStride + n] : 0.f;
    uint32_t h, l;
    split2(w0, w1, h, l);
    dst[(size_t)tile * 2048 + bi] = h;
    dst[(size_t)tile * 2048 + 1024 + bi] = l;
}

__global__ void prep_k(
    uint32_t* __restrict__ WembSp, uint32_t* __restrict__ W1tSp,
    uint32_t* __restrict__ W1bSp, uint32_t* __restrict__ W2Sp,
    uint32_t* __restrict__ W3Sp, uint32_t* __restrict__ Wf1Sp,
    uint32_t* __restrict__ tsp,
    float* __restrict__ b1p, float* __restrict__ b2p, float* __restrict__ b3p,
    float* __restrict__ bf1p, float* __restrict__ Wf2p,
    const float* __restrict__ W_emb, const float* __restrict__ Wg1,
    const float* __restrict__ Wg2, const float* __restrict__ Wg3,
    const float* __restrict__ Wf1, const float* __restrict__ bg1,
    const float* __restrict__ bg2, const float* __restrict__ bg3,
    const float* __restrict__ bf1, const float* __restrict__ Wf2)
{
    int idx = blockIdx.x * blockDim.x + threadIdx.x;
    const int C0 = 4 * 400 * 1024;
    const int C1 = 9 * 33 * 1024;
    const int C3 = 9 * 66 * 1024;
    const int C6 = 64 * 1024;

    if (idx < C0) { wsplit_body(WembSp, W_emb, idx, 400, KE, 512, 512, 0); return; }
    idx -= C0;
    if (idx < C1) { wsplit_body(W1tSp, Wg1, idx, 33, 521, T, T, 0); return; }
    idx -= C1;
    if (idx < C1) { wsplit_body(W1bSp, Wg1, idx, 33, 521, T, T, 521); return; }
    idx -= C1;
    if (idx < C3) { wsplit_body(W2Sp, Wg2, idx, 66, T, T, T, 0); return; }
    idx -= C3;
    if (idx < C3) { wsplit_body(W3Sp, Wg3, idx, 66, T, T, T, 0); return; }
    idx -= C3;
    if (idx < C3) { wsplit_body(Wf1Sp, Wf1, idx, 66, T, T, T, 0); return; }
    idx -= C3;
    if (idx < C6) {
        int ai = idx & 1023;
        int mt = idx >> 10;
        int w = ai & 127, fbv = ai >> 7;
        int lane = w >> 2, rem = w & 3;
        int rb8 = rem & 1, pks = rem >> 1;
        int p8 = lane >> 2, j = lane & 3;
        int r = mt * 128 + fbv * 16 + rb8 * 8 + p8;
        int col = 512 + pks * 8 + 2 * j;
        int tpos = ((r & 15) < 8) ? (r & 15) : 8;
        int tcol = 512 + tpos;
        uint32_t h = 0;
        if (col == tcol)     h |= 0x3F80u;
        if (col + 1 == tcol) h |= 0x3F80u << 16;
        size_t base = ((size_t)mt * 33 + 32) * 2048 + ai;
        tsp[base] = h;
        tsp[base + 1024] = 0u;
        return;
    }
    idx -= C6;
    if (idx < 5 * TP) {
        int v = idx / TP, c = idx % TP;
        const float* s = (v == 0) ? bg1 : (v == 1) ? bg2 : (v == 2) ? bg3
                       : (v == 3) ? bf1 : Wf2;
        float* d = (v == 0) ? b1p : (v == 1) ? b2p : (v == 2) ? b3p
                 : (v == 3) ? bf1p : Wf2p;
        d[c] = (c < T) ? s[c] : 0.f;
    }
}

// ---- H1 expand + split: relu(P[b,j]+Q[b,k]+b1) -> H1Sp -------------------
__global__ void expandsp_k(const float* __restrict__ P, const float* __restrict__ Q,
                           const float* __restrict__ b1, uint32_t* __restrict__ H1sp)
{
    __shared__ float sP[8][16], sQ[16][16], sB[16];
    int b = blockIdx.y, kb = blockIdx.x;
    int t = threadIdx.x;
    int k0 = kb * 16;
    if (t < 96) {
        int row = t >> 2, q = t & 3;
        const float* src = (row < 8) ? (P + (size_t)(b * 16 + row) * TP)
                                     : (Q + (size_t)(b * 16 + row - 8) * TP);
        float4 v = *(const float4*)(src + k0 + q * 4);
        if (row < 8) *(float4*)&sP[row][q * 4] = v;
        else         *(float4*)&sQ[row - 8][q * 4] = v;
    } else if (t < 100) {
        int q = t - 96;
        *(float4*)&sB[q * 4] = *(const float4*)(b1 + k0 + q * 4);
    }
    __syncthreads();
    int L = t & 31;
    int p8 = L >> 2, j = L & 3;
    int fbv = t >> 5;
    uint32_t hi[4], lo[4];
    #pragma unroll
    for (int s = 0; s < 2; s++) {
        int kA = s * 8 + 2 * j;
        #pragma unroll
        for (int rb = 0; rb < 2; rb++) {
            int r = fbv * 16 + rb * 8 + p8;
            int jj = r & 7, kk = r >> 3;
            float e0 = fmaxf(sP[jj][kA]     + sQ[kk][kA]     + sB[kA],     0.f);
            float e1 = fmaxf(sP[jj][kA + 1] + sQ[kk][kA + 1] + sB[kA + 1], 0.f);
            split2(e0, e1, hi[2 * s + rb], lo[2 * s + rb]);
        }
    }
    size_t base = ((size_t)b * 66 + kb) * 2048 + t * 4;
    *(uint4*)(H1sp + base)        = make_uint4(hi[0], hi[1], hi[2], hi[3]);
    *(uint4*)(H1sp + base + 1024) = make_uint4(lo[0], lo[1], lo[2], lo[3]);
}

// ======================= small kernels ====================================
__inline__ __device__ float warp_sum(float v)
{
    #pragma unroll
    for (int o = 16; o; o >>= 1) v += __shfl_down_sync(0xffffffffu, v, o);
    return v;
}

__global__ void loss_k(const float* __restrict__ fo, const int* __restrict__ labels,
                       const float* __restrict__ bf2, float* __restrict__ out)
{
    int b = threadIdx.x;
    int lab = labels[b];
    float bias2 = bf2[0];
    float lsum = 0.f;
    float best = -1e30f; int bi = 0;
    #pragma unroll
    for (int a = 0; a < 8; a++) {
        float f = fo[b * 8 + a] + bias2;
        float l = fmaxf(f, 0.f) - f * ((a == lab) ? 1.f : 0.f) + log1pf(expf(-fabsf(f)));
        lsum += l;
        if (f > best) { best = f; bi = a; }
    }
    float cor = (bi == lab) ? 1.f : 0.f;
    lsum = warp_sum(lsum);
    cor  = warp_sum(cor);
    __shared__ float sl[16], sc[16];
    int wid = threadIdx.x >> 5, lane = threadIdx.x & 31;
    if (lane == 0) { sl[wid] = lsum; sc[wid] = cor; }
    __syncthreads();
    if (wid == 0) {
        float a = (lane < 16) ? sl[lane] : 0.f;
        float c = (lane < 16) ? sc[lane] : 0.f;
        a = warp_sum(a);
        c = warp_sum(c);
        if (lane == 0) {
            out[0] = a / (float)(NBATCH * 8);
            out[1] = c / (float)NBATCH;
        }
    }
}

// ======================= host =============================================
static inline int cdiv(int a, int b) { return (a + b - 1) / b; }

extern "C" void kernel_launch(void* const* d_in, const int* in_sizes, int n_in,
                              void* d_out, int out_size)
{
    const float* x      = (const float*)d_in[0];
    const float* W_emb  = (const float*)d_in[1];
    const float* b_emb  = (const float*)d_in[2];
    const float* Wg1    = (const float*)d_in[3];
    const float* bg1    = (const float*)d_in[4];
    const float* Wg2    = (const float*)d_in[5];
    const float* bg2    = (const float*)d_in[6];
    const float* Wg3    = (const float*)d_in[7];
    const float* bg3    = (const float*)d_in[8];
    const float* Wf1    = (const float*)d_in[9];
    const float* bf1    = (const float*)d_in[10];
    const float* Wf2    = (const float*)d_in[11];
    const float* bf2    = (const float*)d_in[12];
    const int*   labels = (const int*)d_in[13];
    float* out = (float*)d_out;

    float *P, *Q, *rel, *fo;
    float *Wf2p, *b1p, *b2p, *b3p, *bf1p;
    uint32_t *xSp, *taggedSp, *H1Sp, *H2Sp, *WembSp, *W1tSp, *W1bSp, *W2Sp, *W3Sp, *Wf1Sp;
    cudaGetSymbolAddress((void**)&P, g_P);
    cudaGetSymbolAddress((void**)&Q, g_Q);
    cudaGetSymbolAddress((void**)&rel, g_rel);
    cudaGetSymbolAddress((void**)&fo, g_fo);
    cudaGetSymbolAddress((void**)&xSp, g_xSp);
    cudaGetSymbolAddress((void**)&taggedSp, g_taggedSp);
    cudaGetSymbolAddress((void**)&H1Sp, g_H1Sp);
    cudaGetSymbolAddress((void**)&H2Sp, g_H2Sp);
    cudaGetSymbolAddress((void**)&WembSp, g_WembSp);
    cudaGetSymbolAddress((void**)&W1tSp, g_W1tSp);
    cudaGetSymbolAddress((void**)&W1bSp, g_W1bSp);
    cudaGetSymbolAddress((void**)&W2Sp, g_W2Sp);
    cudaGetSymbolAddress((void**)&W3Sp, g_W3Sp);
    cudaGetSymbolAddress((void**)&Wf1Sp, g_Wf1Sp);
    cudaGetSymbolAddress((void**)&Wf2p, g_Wf2p);
    cudaGetSymbolAddress((void**)&b1p, g_b1);
    cudaGetSymbolAddress((void**)&b2p, g_b2);
    cudaGetSymbolAddress((void**)&b3p, g_b3);
    cudaGetSymbolAddress((void**)&bf1p, g_bf1);

    const int SMB2 = 2 * STG * 4;   // 33024 bytes (reg pipeline)
    const int SMB3 = 3 * STG * 4;   // 49536 bytes (cp.async pipeline)
    cudaFuncSetAttribute(mmagemm_k<1,2,1,0>, cudaFuncAttributeMaxDynamicSharedMemorySize, SMB3);
    cudaFuncSetAttribute(mmagemm_k<0,2,0,1>, cudaFuncAttributeMaxDynamicSharedMemorySize, SMB3);
    cudaFuncSetAttribute(mmagemm_k<2,2,1,1>, cudaFuncAttributeMaxDynamicSharedMemorySize, SMB3);
    cudaFuncSetAttribute(mmagemm_k<5,2,0,1>, cudaFuncAttributeMaxDynamicSharedMemorySize, SMB3);
    cudaFuncSetAttribute(mmagemm_k<4,0,0,1>, cudaFuncAttributeMaxDynamicSharedMemorySize, SMB2);

    // ---- one-time prep: all weight splits + tags + bias pads (1 launch) ----
    const int PREP_TOTAL = 4*400*1024 + 2*9*33*1024 + 3*9*66*1024 + 64*1024 + 5*TP;
    prep_k<<<cdiv(PREP_TOTAL, 256), 256>>>(
        WembSp, W1tSp, W1bSp, W2Sp, W3Sp, Wf1Sp, taggedSp,
        b1p, b2p, b3p, bf1p, Wf2p,
        W_emb, Wg1, Wg2, Wg3, Wf1, bg1, bg2, bg3, bf1, Wf2);
    // pre-split x into A-fragment layout
    xsplit_k<<<dim3(50, 64), 256>>>(xSp, x);
    cudaMemsetAsync(fo, 0, M_REL * sizeof(float));

    // emb = x @ W_emb + b_emb -> taggedSp (cp.async; kb 0..31 data, kb 32 tags)
    mmagemm_k<1,2,1,0><<<dim3(4, M_EMB / 128), 256, SMB3>>>(
        nullptr, 0, xSp, WembSp, 512, nullptr, 0, taggedSp, 33, KE, b_emb, nullptr);
    // P = tagged @ Wg1_top ; Q = tagged @ Wg1_bot  (cp.async, narrow 9th tile)
    mmagemm_k<0,2,0,1><<<dim3(9, M_EMB / 128), 256, SMB3>>>(
        nullptr, 0, taggedSp, W1tSp, TP, P, TP, nullptr, 0, KT, nullptr, nullptr);
    mmagemm_k<0,2,0,1><<<dim3(9, M_EMB / 128), 256, SMB3>>>(
        nullptr, 0, taggedSp, W1bSp, TP, Q, TP, nullptr, 0, KT, nullptr, nullptr);
    // H1 = relu(P[j]+Q[k]+b1), split once into H1Sp
    expandsp_k<<<dim3(66, NBATCH), 256>>>(P, Q, b1p, H1Sp);
    // L2: H2 = relu(H1 @ Wg2 + b2) -> H2Sp (split layout)
    mmagemm_k<2,2,1,1><<<dim3(9, M_PAIR / 128), 256, SMB3>>>(
        nullptr, 0, H1Sp, W2Sp, TP, nullptr, 0, H2Sp, 66, TP, b2p, nullptr);
    // L3: relations fused — 8-row sums + cross-k combine -> rel
    mmagemm_k<5,2,0,1><<<dim3(9, M_PAIR / 128), 256, SMB3>>>(
        nullptr, 0, H2Sp, W3Sp, TP, rel, TP, nullptr, 0, TP, b3p, nullptr);
    // f: Hf = relu(rel @ Wf1 + bf1); f_out partial-dot fused via atomics -> fo
    mmagemm_k<4,0,0,1><<<dim3(9, M_REL / 128), 256, SMB2>>>(
        rel, TP, nullptr, Wf1Sp, TP, fo, TP, nullptr, 0, TP, bf1p, Wf2p);
    loss_k<<<1, 512>>>(fo, labels, bf2, out);
}